// round 1
// baseline (speedup 1.0000x reference)
#include <cuda_runtime.h>
#include <math.h>

// Problem constants (GPT_5875515261622)
#define NL   4
#define NH   12
#define EDIM 768
#define TDIM 1024
#define BDIM 2
#define VDIM 50257
#define HD   64
#define BT   (BDIM*TDIM)

// ---- scratch (device globals; no runtime allocation allowed) ----
__device__ float g_x  [BT*EDIM];
__device__ float g_h  [BT*EDIM];
__device__ float g_qkv[BT*3*EDIM];
__device__ float g_att[(long long)BDIM*NH*TDIM*TDIM];
__device__ float g_y  [BT*EDIM];
__device__ float g_m  [BT*4*EDIM];

// ---- embedding: x = wte[idx] + wpe[t] ----
__global__ void embed_kernel(const int* __restrict__ idx,
                             const float* __restrict__ wte,
                             const float* __restrict__ wpe) {
    int row = blockIdx.x;              // 0..BT-1
    int t   = row % TDIM;
    long long tok = idx[row];
    const float* src = wte + tok * EDIM;
    const float* pos = wpe + (long long)t * EDIM;
    float* dst = g_x + (long long)row * EDIM;
    for (int c = threadIdx.x; c < EDIM; c += blockDim.x)
        dst[c] = src[c] + pos[c];
}

// ---- layernorm (one block per row) ----
__global__ void layernorm_kernel(const float* __restrict__ in,
                                 float* __restrict__ out,
                                 const float* __restrict__ w,
                                 const float* __restrict__ b) {
    int row = blockIdx.x;
    const float* x = in + (long long)row * EDIM;
    float* o = out + (long long)row * EDIM;
    __shared__ float red[256];
    float s = 0.f;
    for (int c = threadIdx.x; c < EDIM; c += blockDim.x) s += x[c];
    red[threadIdx.x] = s; __syncthreads();
    for (int st = 128; st > 0; st >>= 1) {
        if (threadIdx.x < st) red[threadIdx.x] += red[threadIdx.x + st];
        __syncthreads();
    }
    float mu = red[0] * (1.f / EDIM);
    __syncthreads();
    float v = 0.f;
    for (int c = threadIdx.x; c < EDIM; c += blockDim.x) { float d = x[c] - mu; v += d * d; }
    red[threadIdx.x] = v; __syncthreads();
    for (int st = 128; st > 0; st >>= 1) {
        if (threadIdx.x < st) red[threadIdx.x] += red[threadIdx.x + st];
        __syncthreads();
    }
    float rstd = rsqrtf(red[0] * (1.f / EDIM) + 1e-5f);
    for (int c = threadIdx.x; c < EDIM; c += blockDim.x)
        o[c] = (x[c] - mu) * rstd * w[c] + b[c];
}

// ---- causal softmax, in-place on g_att; zeros the masked tail ----
__global__ void softmax_kernel() {
    int i = blockIdx.x;                 // query index
    long long z = blockIdx.y;           // b*NH + h
    float* row = g_att + (z * TDIM + i) * (long long)TDIM;
    int n = i + 1;
    __shared__ float red[128];
    float mx = -1e30f;
    for (int j = threadIdx.x; j < n; j += blockDim.x) mx = fmaxf(mx, row[j]);
    red[threadIdx.x] = mx; __syncthreads();
    for (int st = 64; st > 0; st >>= 1) {
        if (threadIdx.x < st) red[threadIdx.x] = fmaxf(red[threadIdx.x], red[threadIdx.x + st]);
        __syncthreads();
    }
    mx = red[0]; __syncthreads();
    float s = 0.f;
    for (int j = threadIdx.x; j < n; j += blockDim.x) { float e = __expf(row[j] - mx); row[j] = e; s += e; }
    red[threadIdx.x] = s; __syncthreads();
    for (int st = 64; st > 0; st >>= 1) {
        if (threadIdx.x < st) red[threadIdx.x] += red[threadIdx.x + st];
        __syncthreads();
    }
    float inv = 1.f / red[0];
    for (int j = threadIdx.x; j < n; j += blockDim.x) row[j] *= inv;
    for (int j = n + threadIdx.x; j < TDIM; j += blockDim.x) row[j] = 0.f;
}

// ---- generic fp32 GEMM: C = alpha*(A@B[^T]) + bias [+gelu | +residual] ----
// Batched via blockIdx.z with two-level offset: z -> (zb = z/zdiv, zh = z%zdiv).
// TB: 0 -> B is [K,N] row-major; 1 -> B is [N,K] row-major (B^T)
// EP: 0 none, 1 gelu(tanh), 2 add residual res (same layout as C)
template<int TB, int EP>
__global__ void gemm_kernel(const float* __restrict__ A, long long sAb, long long sAh,
                            const float* __restrict__ Bm, long long sBb, long long sBh,
                            float* __restrict__ C, long long sCb, long long sCh,
                            const float* __restrict__ bias,
                            const float* __restrict__ res,
                            int M, int N, int K, int lda, int ldb, int ldc,
                            float alpha, int zdiv)
{
    const int BK = 16;
    __shared__ float As[BK][132];
    __shared__ float Bs[BK][132];

    int z = blockIdx.z;
    int zb = z / zdiv, zh = z % zdiv;
    A  += zb * sAb + zh * sAh;
    Bm += zb * sBb + zh * sBh;
    C  += zb * sCb + zh * sCh;

    int m0 = blockIdx.y * 128;
    int n0 = blockIdx.x * 128;
    int tid = threadIdx.x;
    int tx = tid & 15, ty = tid >> 4;

    float acc[8][8];
    #pragma unroll
    for (int i = 0; i < 8; i++)
        #pragma unroll
        for (int j = 0; j < 8; j++) acc[i][j] = 0.f;

    for (int k0 = 0; k0 < K; k0 += BK) {
        #pragma unroll
        for (int t = 0; t < 8; t++) {
            int idx = tid + t * 256;
            int r = idx >> 4, c = idx & 15;
            int gr = m0 + r;
            As[c][r] = (gr < M) ? A[(long long)gr * lda + k0 + c] : 0.f;
        }
        if (TB == 0) {
            #pragma unroll
            for (int t = 0; t < 8; t++) {
                int idx = tid + t * 256;
                int r = idx >> 7, c = idx & 127;
                int gc = n0 + c;
                Bs[r][c] = (gc < N) ? Bm[(long long)(k0 + r) * ldb + gc] : 0.f;
            }
        } else {
            #pragma unroll
            for (int t = 0; t < 8; t++) {
                int idx = tid + t * 256;
                int nn = idx >> 4, kk = idx & 15;
                int gc = n0 + nn;
                Bs[kk][nn] = (gc < N) ? Bm[(long long)gc * ldb + k0 + kk] : 0.f;
            }
        }
        __syncthreads();
        #pragma unroll
        for (int k = 0; k < BK; k++) {
            float a[8], b[8];
            *(float4*)&a[0] = *(const float4*)&As[k][ty * 4];
            *(float4*)&a[4] = *(const float4*)&As[k][64 + ty * 4];
            *(float4*)&b[0] = *(const float4*)&Bs[k][tx * 4];
            *(float4*)&b[4] = *(const float4*)&Bs[k][64 + tx * 4];
            #pragma unroll
            for (int i = 0; i < 8; i++)
                #pragma unroll
                for (int j = 0; j < 8; j++)
                    acc[i][j] += a[i] * b[j];
        }
        __syncthreads();
    }

    #pragma unroll
    for (int i = 0; i < 8; i++) {
        int ri = (i < 4) ? (ty * 4 + i) : (64 + ty * 4 + i - 4);
        int r = m0 + ri;
        if (r >= M) continue;
        #pragma unroll
        for (int j = 0; j < 8; j++) {
            int cj = (j < 4) ? (tx * 4 + j) : (64 + tx * 4 + j - 4);
            int c = n0 + cj;
            if (c >= N) continue;
            float v = alpha * acc[i][j];
            if (bias) v += bias[c];
            if (EP == 1) {
                float u = v;
                v = 0.5f * u * (1.f + tanhf(0.7978845608028654f * (u + 0.044715f * u * u * u)));
            }
            if (EP == 2) v += res[(long long)r * ldc + c];
            C[(long long)r * ldc + c] = v;
        }
    }
}

extern "C" void kernel_launch(void* const* d_in, const int* in_sizes, int n_in,
                              void* d_out, int out_size) {
    const int*   idx    = (const int*)  d_in[0];
    const float* wte    = (const float*)d_in[1];
    const float* wpe    = (const float*)d_in[2];
    const float* ln1_w  = (const float*)d_in[3];
    const float* ln1_b  = (const float*)d_in[4];
    const float* attn_w = (const float*)d_in[5];
    const float* attn_b = (const float*)d_in[6];
    const float* atp_w  = (const float*)d_in[7];
    const float* atp_b  = (const float*)d_in[8];
    const float* ln2_w  = (const float*)d_in[9];
    const float* ln2_b  = (const float*)d_in[10];
    const float* fc_w   = (const float*)d_in[11];
    const float* fc_b   = (const float*)d_in[12];
    const float* pr_w   = (const float*)d_in[13];
    const float* pr_b   = (const float*)d_in[14];
    const float* lnf_w  = (const float*)d_in[15];
    const float* lnf_b  = (const float*)d_in[16];
    float* out = (float*)d_out;

    float *gx, *gh, *gqkv, *gatt, *gy, *gm;
    cudaGetSymbolAddress((void**)&gx,   g_x);
    cudaGetSymbolAddress((void**)&gh,   g_h);
    cudaGetSymbolAddress((void**)&gqkv, g_qkv);
    cudaGetSymbolAddress((void**)&gatt, g_att);
    cudaGetSymbolAddress((void**)&gy,   g_y);
    cudaGetSymbolAddress((void**)&gm,   g_m);

    const float scale = 0.03608439182435161f;  // 1/sqrt(E)

    embed_kernel<<<BT, 256>>>(idx, wte, wpe);

    for (int l = 0; l < NL; l++) {
        // h = LN1(x)
        layernorm_kernel<<<BT, 256>>>(gx, gh, ln1_w + l * EDIM, ln1_b + l * EDIM);

        // qkv = h @ attn_w + attn_b   [BT, 3E]
        {
            dim3 g((3 * EDIM + 127) / 128, (BT + 127) / 128, 1);
            gemm_kernel<0, 0><<<g, 256>>>(gh, 0, 0,
                                          attn_w + (long long)l * EDIM * 3 * EDIM, 0, 0,
                                          gqkv, 0, 0,
                                          attn_b + l * 3 * EDIM, nullptr,
                                          BT, 3 * EDIM, EDIM, EDIM, 3 * EDIM, 3 * EDIM,
                                          1.f, 1);
        }
        // scores = scale * Q @ K^T  (batched over B*H)
        {
            dim3 g(TDIM / 128, TDIM / 128, BDIM * NH);
            gemm_kernel<1, 0><<<g, 256>>>(gqkv, (long long)TDIM * 3 * EDIM, HD,
                                          gqkv + EDIM, (long long)TDIM * 3 * EDIM, HD,
                                          gatt, (long long)NH * TDIM * TDIM, (long long)TDIM * TDIM,
                                          nullptr, nullptr,
                                          TDIM, TDIM, HD, 3 * EDIM, 3 * EDIM, TDIM,
                                          scale, NH);
        }
        // causal softmax in-place
        {
            dim3 g(TDIM, BDIM * NH);
            softmax_kernel<<<g, 128>>>();
        }
        // y = attn @ V  (batched)
        {
            dim3 g(1, TDIM / 128, BDIM * NH);
            gemm_kernel<0, 0><<<g, 256>>>(gatt, (long long)NH * TDIM * TDIM, (long long)TDIM * TDIM,
                                          gqkv + 2 * EDIM, (long long)TDIM * 3 * EDIM, HD,
                                          gy, (long long)TDIM * EDIM, HD,
                                          nullptr, nullptr,
                                          TDIM, HD, TDIM, TDIM, 3 * EDIM, EDIM,
                                          1.f, NH);
        }
        // x = x + y @ atp_w + atp_b
        {
            dim3 g((EDIM + 127) / 128, (BT + 127) / 128, 1);
            gemm_kernel<0, 2><<<g, 256>>>(gy, 0, 0,
                                          atp_w + (long long)l * EDIM * EDIM, 0, 0,
                                          gx, 0, 0,
                                          atp_b + l * EDIM, gx,
                                          BT, EDIM, EDIM, EDIM, EDIM, EDIM,
                                          1.f, 1);
        }
        // h = LN2(x)
        layernorm_kernel<<<BT, 256>>>(gx, gh, ln2_w + l * EDIM, ln2_b + l * EDIM);

        // m = gelu(h @ fc_w + fc_b)   [BT, 4E]
        {
            dim3 g((4 * EDIM + 127) / 128, (BT + 127) / 128, 1);
            gemm_kernel<0, 1><<<g, 256>>>(gh, 0, 0,
                                          fc_w + (long long)l * EDIM * 4 * EDIM, 0, 0,
                                          gm, 0, 0,
                                          fc_b + l * 4 * EDIM, nullptr,
                                          BT, 4 * EDIM, EDIM, EDIM, 4 * EDIM, 4 * EDIM,
                                          1.f, 1);
        }
        // x = x + m @ pr_w + pr_b
        {
            dim3 g((EDIM + 127) / 128, (BT + 127) / 128, 1);
            gemm_kernel<0, 2><<<g, 256>>>(gm, 0, 0,
                                          pr_w + (long long)l * 4 * EDIM * EDIM, 0, 0,
                                          gx, 0, 0,
                                          pr_b + l * EDIM, gx,
                                          BT, EDIM, 4 * EDIM, 4 * EDIM, EDIM, EDIM,
                                          1.f, 1);
        }
    }

    // h = LN_f(x)
    layernorm_kernel<<<BT, 256>>>(gx, gh, lnf_w, lnf_b);

    // logits = h @ wte^T   [BT, V]
    {
        dim3 g((VDIM + 127) / 128, (BT + 127) / 128, 1);
        gemm_kernel<1, 0><<<g, 256>>>(gh, 0, 0,
                                      wte, 0, 0,
                                      out, 0, 0,
                                      nullptr, nullptr,
                                      BT, VDIM, EDIM, EDIM, EDIM, VDIM,
                                      1.f, 1);
    }
}

// round 2
// speedup vs baseline: 2.6377x; 2.6377x over previous
#include <cuda_runtime.h>
#include <math.h>

// Problem constants (GPT_5875515261622)
#define NL   4
#define NH   12
#define EDIM 768
#define TDIM 1024
#define BDIM 2
#define VDIM 50257
#define HD   64
#define BT   (BDIM*TDIM)

// ---- scratch (device globals; no runtime allocation allowed) ----
__device__ float g_x  [BT*EDIM];
__device__ float g_h  [BT*EDIM];
__device__ float g_qkv[BT*3*EDIM];
__device__ float g_att[(long long)BDIM*NH*TDIM*TDIM];
__device__ float g_y  [BT*EDIM];
__device__ float g_m  [BT*4*EDIM];

// ---- embedding: x = wte[idx] + wpe[t] ----
__global__ void embed_kernel(const int* __restrict__ idx,
                             const float* __restrict__ wte,
                             const float* __restrict__ wpe) {
    int row = blockIdx.x;
    int t   = row % TDIM;
    long long tok = idx[row];
    const float* src = wte + tok * EDIM;
    const float* pos = wpe + (long long)t * EDIM;
    float* dst = g_x + (long long)row * EDIM;
    for (int c = threadIdx.x; c < EDIM; c += blockDim.x)
        dst[c] = src[c] + pos[c];
}

// ---- layernorm (one block per row) ----
__global__ void layernorm_kernel(const float* __restrict__ in,
                                 float* __restrict__ out,
                                 const float* __restrict__ w,
                                 const float* __restrict__ b) {
    int row = blockIdx.x;
    const float* x = in + (long long)row * EDIM;
    float* o = out + (long long)row * EDIM;
    __shared__ float red[256];
    float s = 0.f;
    for (int c = threadIdx.x; c < EDIM; c += blockDim.x) s += x[c];
    red[threadIdx.x] = s; __syncthreads();
    for (int st = 128; st > 0; st >>= 1) {
        if (threadIdx.x < st) red[threadIdx.x] += red[threadIdx.x + st];
        __syncthreads();
    }
    float mu = red[0] * (1.f / EDIM);
    __syncthreads();
    float v = 0.f;
    for (int c = threadIdx.x; c < EDIM; c += blockDim.x) { float d = x[c] - mu; v += d * d; }
    red[threadIdx.x] = v; __syncthreads();
    for (int st = 128; st > 0; st >>= 1) {
        if (threadIdx.x < st) red[threadIdx.x] += red[threadIdx.x + st];
        __syncthreads();
    }
    float rstd = rsqrtf(red[0] * (1.f / EDIM) + 1e-5f);
    for (int c = threadIdx.x; c < EDIM; c += blockDim.x)
        o[c] = (x[c] - mu) * rstd * w[c] + b[c];
}

// ---- causal softmax, in-place on g_att; zeros the masked tail ----
__global__ void softmax_kernel() {
    int i = blockIdx.x;
    long long z = blockIdx.y;
    float* row = g_att + (z * TDIM + i) * (long long)TDIM;
    int n = i + 1;
    __shared__ float red[128];
    float mx = -1e30f;
    for (int j = threadIdx.x; j < n; j += blockDim.x) mx = fmaxf(mx, row[j]);
    red[threadIdx.x] = mx; __syncthreads();
    for (int st = 64; st > 0; st >>= 1) {
        if (threadIdx.x < st) red[threadIdx.x] = fmaxf(red[threadIdx.x], red[threadIdx.x + st]);
        __syncthreads();
    }
    mx = red[0]; __syncthreads();
    float s = 0.f;
    for (int j = threadIdx.x; j < n; j += blockDim.x) { float e = __expf(row[j] - mx); row[j] = e; s += e; }
    red[threadIdx.x] = s; __syncthreads();
    for (int st = 64; st > 0; st >>= 1) {
        if (threadIdx.x < st) red[threadIdx.x] += red[threadIdx.x + st];
        __syncthreads();
    }
    float inv = 1.f / red[0];
    for (int j = threadIdx.x; j < n; j += blockDim.x) row[j] *= inv;
    for (int j = n + threadIdx.x; j < TDIM; j += blockDim.x) row[j] = 0.f;
}

__device__ __forceinline__ unsigned f2tf(float x) {
    unsigned u;
    asm("cvt.rna.tf32.f32 %0, %1;" : "=r"(u) : "f"(x));
    return u;
}

// ---- tf32 tensor-core GEMM: C = alpha*(A@B[^T]) + bias [+gelu | +residual] ----
// CTA tile 128x128, BK=32, 8 warps of 32x64 warp-tiles, mma.m16n8k8.tf32.
// TB: 0 -> B is [K,N] row-major; 1 -> B is [N,K] row-major (B^T)
// EP: 0 none, 1 gelu(tanh), 2 add residual res
template<int TB, int EP>
__global__ void __launch_bounds__(256, 2)
gemm_tc(const float* __restrict__ A, long long sAb, long long sAh,
        const float* __restrict__ Bm, long long sBb, long long sBh,
        float* __restrict__ C, long long sCb, long long sCh,
        const float* __restrict__ bias,
        const float* __restrict__ res,
        int M, int N, int K, int lda, int ldb, int ldc,
        float alpha, int zdiv)
{
    // As: [128][36] m-major. Bsm: TB0 [32][136] k-major, TB1 [128][36] n-major.
    __shared__ float As[128 * 36];
    __shared__ float Bsm[128 * 36];

    int z = blockIdx.z;
    int zb = z / zdiv, zh = z % zdiv;
    A  += zb * sAb + zh * sAh;
    Bm += zb * sBb + zh * sBh;
    C  += zb * sCb + zh * sCh;

    const int m0 = blockIdx.y * 128;
    const int n0 = blockIdx.x * 128;
    const int tid = threadIdx.x;
    const int warp = tid >> 5, lane = tid & 31;
    const int g = lane >> 2, tg = lane & 3;
    const int wm = warp >> 1, wn = warp & 1;

    float acc[2][8][4];
    #pragma unroll
    for (int mt = 0; mt < 2; mt++)
        #pragma unroll
        for (int nt = 0; nt < 8; nt++)
            #pragma unroll
            for (int c = 0; c < 4; c++) acc[mt][nt][c] = 0.f;

    const float4 z4 = make_float4(0.f, 0.f, 0.f, 0.f);

    for (int k0 = 0; k0 < K; k0 += 32) {
        // --- A tile: 128x32, float4, coalesced ---
        #pragma unroll
        for (int it = 0; it < 4; it++) {
            int idx = tid + it * 256;
            int row = idx >> 3, c4 = (idx & 7) * 4;
            int gr = m0 + row;
            float4 v = (gr < M) ? *(const float4*)&A[(long long)gr * lda + k0 + c4] : z4;
            *(float4*)&As[row * 36 + c4] = v;
        }
        // --- B tile ---
        if (TB == 0) {
            #pragma unroll
            for (int it = 0; it < 4; it++) {
                int idx = tid + it * 256;
                int r = idx >> 5, c4 = (idx & 31) * 4;
                int gc = n0 + c4;
                float4 v = (gc < N) ? *(const float4*)&Bm[(long long)(k0 + r) * ldb + gc] : z4;
                *(float4*)&Bsm[r * 136 + c4] = v;
            }
        } else {
            #pragma unroll
            for (int it = 0; it < 4; it++) {
                int idx = tid + it * 256;
                int nn = idx >> 3, kc4 = (idx & 7) * 4;
                int gn = n0 + nn;
                float4 v = (gn < N) ? *(const float4*)&Bm[(long long)gn * ldb + k0 + kc4] : z4;
                *(float4*)&Bsm[nn * 36 + kc4] = v;
            }
        }
        __syncthreads();

        #pragma unroll
        for (int kk = 0; kk < 4; kk++) {
            const int kb = kk * 8;
            unsigned af[2][4];
            #pragma unroll
            for (int mt = 0; mt < 2; mt++) {
                int rb = wm * 32 + mt * 16;
                af[mt][0] = f2tf(As[(rb + g) * 36 + kb + tg]);
                af[mt][1] = f2tf(As[(rb + g + 8) * 36 + kb + tg]);
                af[mt][2] = f2tf(As[(rb + g) * 36 + kb + tg + 4]);
                af[mt][3] = f2tf(As[(rb + g + 8) * 36 + kb + tg + 4]);
            }
            unsigned bf[8][2];
            #pragma unroll
            for (int nt = 0; nt < 8; nt++) {
                int col = wn * 64 + nt * 8 + g;
                if (TB == 0) {
                    bf[nt][0] = f2tf(Bsm[(kb + tg) * 136 + col]);
                    bf[nt][1] = f2tf(Bsm[(kb + tg + 4) * 136 + col]);
                } else {
                    bf[nt][0] = f2tf(Bsm[col * 36 + kb + tg]);
                    bf[nt][1] = f2tf(Bsm[col * 36 + kb + tg + 4]);
                }
            }
            #pragma unroll
            for (int mt = 0; mt < 2; mt++)
                #pragma unroll
                for (int nt = 0; nt < 8; nt++) {
                    asm volatile(
                        "mma.sync.aligned.m16n8k8.row.col.f32.tf32.tf32.f32 "
                        "{%0,%1,%2,%3}, {%4,%5,%6,%7}, {%8,%9}, {%0,%1,%2,%3};\n"
                        : "+f"(acc[mt][nt][0]), "+f"(acc[mt][nt][1]),
                          "+f"(acc[mt][nt][2]), "+f"(acc[mt][nt][3])
                        : "r"(af[mt][0]), "r"(af[mt][1]), "r"(af[mt][2]), "r"(af[mt][3]),
                          "r"(bf[nt][0]), "r"(bf[nt][1]));
                }
        }
        __syncthreads();
    }

    // ---- epilogue ----
    #pragma unroll
    for (int mt = 0; mt < 2; mt++) {
        #pragma unroll
        for (int nt = 0; nt < 8; nt++) {
            int col = n0 + wn * 64 + nt * 8 + 2 * tg;
            int r0 = m0 + wm * 32 + mt * 16 + g;
            #pragma unroll
            for (int ci = 0; ci < 4; ci++) {
                int r = r0 + (ci >> 1) * 8;
                int c = col + (ci & 1);
                if (r >= M || c >= N) continue;
                float v = alpha * acc[mt][nt][ci];
                if (bias) v += bias[c];
                if (EP == 1) {
                    float u = v;
                    v = 0.5f * u * (1.f + tanhf(0.7978845608028654f * (u + 0.044715f * u * u * u)));
                }
                if (EP == 2) v += res[(long long)r * ldc + c];
                C[(long long)r * ldc + c] = v;
            }
        }
    }
}

extern "C" void kernel_launch(void* const* d_in, const int* in_sizes, int n_in,
                              void* d_out, int out_size) {
    const int*   idx    = (const int*)  d_in[0];
    const float* wte    = (const float*)d_in[1];
    const float* wpe    = (const float*)d_in[2];
    const float* ln1_w  = (const float*)d_in[3];
    const float* ln1_b  = (const float*)d_in[4];
    const float* attn_w = (const float*)d_in[5];
    const float* attn_b = (const float*)d_in[6];
    const float* atp_w  = (const float*)d_in[7];
    const float* atp_b  = (const float*)d_in[8];
    const float* ln2_w  = (const float*)d_in[9];
    const float* ln2_b  = (const float*)d_in[10];
    const float* fc_w   = (const float*)d_in[11];
    const float* fc_b   = (const float*)d_in[12];
    const float* pr_w   = (const float*)d_in[13];
    const float* pr_b   = (const float*)d_in[14];
    const float* lnf_w  = (const float*)d_in[15];
    const float* lnf_b  = (const float*)d_in[16];
    float* out = (float*)d_out;

    float *gx, *gh, *gqkv, *gatt, *gy, *gm;
    cudaGetSymbolAddress((void**)&gx,   g_x);
    cudaGetSymbolAddress((void**)&gh,   g_h);
    cudaGetSymbolAddress((void**)&gqkv, g_qkv);
    cudaGetSymbolAddress((void**)&gatt, g_att);
    cudaGetSymbolAddress((void**)&gy,   g_y);
    cudaGetSymbolAddress((void**)&gm,   g_m);

    const float scale = 0.03608439182435161f;  // 1/sqrt(E)

    embed_kernel<<<BT, 256>>>(idx, wte, wpe);

    for (int l = 0; l < NL; l++) {
        layernorm_kernel<<<BT, 256>>>(gx, gh, ln1_w + l * EDIM, ln1_b + l * EDIM);

        // qkv = h @ attn_w + attn_b
        {
            dim3 g((3 * EDIM + 127) / 128, (BT + 127) / 128, 1);
            gemm_tc<0, 0><<<g, 256>>>(gh, 0, 0,
                                      attn_w + (long long)l * EDIM * 3 * EDIM, 0, 0,
                                      gqkv, 0, 0,
                                      attn_b + l * 3 * EDIM, nullptr,
                                      BT, 3 * EDIM, EDIM, EDIM, 3 * EDIM, 3 * EDIM,
                                      1.f, 1);
        }
        // scores = scale * Q @ K^T
        {
            dim3 g(TDIM / 128, TDIM / 128, BDIM * NH);
            gemm_tc<1, 0><<<g, 256>>>(gqkv, (long long)TDIM * 3 * EDIM, HD,
                                      gqkv + EDIM, (long long)TDIM * 3 * EDIM, HD,
                                      gatt, (long long)NH * TDIM * TDIM, (long long)TDIM * TDIM,
                                      nullptr, nullptr,
                                      TDIM, TDIM, HD, 3 * EDIM, 3 * EDIM, TDIM,
                                      scale, NH);
        }
        {
            dim3 g(TDIM, BDIM * NH);
            softmax_kernel<<<g, 128>>>();
        }
        // y = attn @ V
        {
            dim3 g(1, TDIM / 128, BDIM * NH);
            gemm_tc<0, 0><<<g, 256>>>(gatt, (long long)NH * TDIM * TDIM, (long long)TDIM * TDIM,
                                      gqkv + 2 * EDIM, (long long)TDIM * 3 * EDIM, HD,
                                      gy, (long long)TDIM * EDIM, HD,
                                      nullptr, nullptr,
                                      TDIM, HD, TDIM, TDIM, 3 * EDIM, EDIM,
                                      1.f, NH);
        }
        // x = x + y @ atp_w + atp_b
        {
            dim3 g((EDIM + 127) / 128, (BT + 127) / 128, 1);
            gemm_tc<0, 2><<<g, 256>>>(gy, 0, 0,
                                      atp_w + (long long)l * EDIM * EDIM, 0, 0,
                                      gx, 0, 0,
                                      atp_b + l * EDIM, gx,
                                      BT, EDIM, EDIM, EDIM, EDIM, EDIM,
                                      1.f, 1);
        }
        layernorm_kernel<<<BT, 256>>>(gx, gh, ln2_w + l * EDIM, ln2_b + l * EDIM);

        // m = gelu(h @ fc_w + fc_b)
        {
            dim3 g((4 * EDIM + 127) / 128, (BT + 127) / 128, 1);
            gemm_tc<0, 1><<<g, 256>>>(gh, 0, 0,
                                      fc_w + (long long)l * EDIM * 4 * EDIM, 0, 0,
                                      gm, 0, 0,
                                      fc_b + l * 4 * EDIM, nullptr,
                                      BT, 4 * EDIM, EDIM, EDIM, 4 * EDIM, 4 * EDIM,
                                      1.f, 1);
        }
        // x = x + m @ pr_w + pr_b
        {
            dim3 g((EDIM + 127) / 128, (BT + 127) / 128, 1);
            gemm_tc<0, 2><<<g, 256>>>(gm, 0, 0,
                                      pr_w + (long long)l * 4 * EDIM * EDIM, 0, 0,
                                      gx, 0, 0,
                                      pr_b + l * EDIM, gx,
                                      BT, EDIM, 4 * EDIM, 4 * EDIM, EDIM, EDIM,
                                      1.f, 1);
        }
    }

    layernorm_kernel<<<BT, 256>>>(gx, gh, lnf_w, lnf_b);

    // logits = h @ wte^T
    {
        dim3 g((VDIM + 127) / 128, (BT + 127) / 128, 1);
        gemm_tc<1, 0><<<g, 256>>>(gh, 0, 0,
                                  wte, 0, 0,
                                  out, 0, 0,
                                  nullptr, nullptr,
                                  BT, VDIM, EDIM, EDIM, EDIM, VDIM,
                                  1.f, 1);
    }
}

// round 3
// speedup vs baseline: 2.6994x; 1.0234x over previous
#include <cuda_runtime.h>
#include <math.h>

// Problem constants (GPT_5875515261622)
#define NL   4
#define NH   12
#define EDIM 768
#define TDIM 1024
#define BDIM 2
#define VDIM 50257
#define HD   64
#define BT   (BDIM*TDIM)

// ---- scratch (device globals; no runtime allocation allowed) ----
__device__ float g_x  [BT*EDIM];
__device__ float g_h  [BT*EDIM];
__device__ float g_qkv[BT*3*EDIM];
__device__ float g_att[(long long)BDIM*NH*TDIM*TDIM];
__device__ float g_y  [BT*EDIM];
__device__ float g_m  [BT*4*EDIM];

// ---- embedding: x = wte[idx] + wpe[t] ----
__global__ void embed_kernel(const int* __restrict__ idx,
                             const float* __restrict__ wte,
                             const float* __restrict__ wpe) {
    int row = blockIdx.x;
    int t   = row % TDIM;
    long long tok = idx[row];
    const float* src = wte + tok * EDIM;
    const float* pos = wpe + (long long)t * EDIM;
    float* dst = g_x + (long long)row * EDIM;
    for (int c = threadIdx.x; c < EDIM; c += blockDim.x)
        dst[c] = src[c] + pos[c];
}

// ---- layernorm (one block per row) ----
__global__ void layernorm_kernel(const float* __restrict__ in,
                                 float* __restrict__ out,
                                 const float* __restrict__ w,
                                 const float* __restrict__ b) {
    int row = blockIdx.x;
    const float* x = in + (long long)row * EDIM;
    float* o = out + (long long)row * EDIM;
    __shared__ float red[256];
    float s = 0.f;
    for (int c = threadIdx.x; c < EDIM; c += blockDim.x) s += x[c];
    red[threadIdx.x] = s; __syncthreads();
    for (int st = 128; st > 0; st >>= 1) {
        if (threadIdx.x < st) red[threadIdx.x] += red[threadIdx.x + st];
        __syncthreads();
    }
    float mu = red[0] * (1.f / EDIM);
    __syncthreads();
    float v = 0.f;
    for (int c = threadIdx.x; c < EDIM; c += blockDim.x) { float d = x[c] - mu; v += d * d; }
    red[threadIdx.x] = v; __syncthreads();
    for (int st = 128; st > 0; st >>= 1) {
        if (threadIdx.x < st) red[threadIdx.x] += red[threadIdx.x + st];
        __syncthreads();
    }
    float rstd = rsqrtf(red[0] * (1.f / EDIM) + 1e-5f);
    for (int c = threadIdx.x; c < EDIM; c += blockDim.x)
        o[c] = (x[c] - mu) * rstd * w[c] + b[c];
}

// ---- causal softmax, in-place on g_att; zeros the masked tail ----
__global__ void softmax_kernel() {
    int i = blockIdx.x;
    long long z = blockIdx.y;
    float* row = g_att + (z * TDIM + i) * (long long)TDIM;
    int n = i + 1;
    __shared__ float red[128];
    float mx = -1e30f;
    for (int j = threadIdx.x; j < n; j += blockDim.x) mx = fmaxf(mx, row[j]);
    red[threadIdx.x] = mx; __syncthreads();
    for (int st = 64; st > 0; st >>= 1) {
        if (threadIdx.x < st) red[threadIdx.x] = fmaxf(red[threadIdx.x], red[threadIdx.x + st]);
        __syncthreads();
    }
    mx = red[0]; __syncthreads();
    float s = 0.f;
    for (int j = threadIdx.x; j < n; j += blockDim.x) { float e = __expf(row[j] - mx); row[j] = e; s += e; }
    red[threadIdx.x] = s; __syncthreads();
    for (int st = 64; st > 0; st >>= 1) {
        if (threadIdx.x < st) red[threadIdx.x] += red[threadIdx.x + st];
        __syncthreads();
    }
    float inv = 1.f / red[0];
    for (int j = threadIdx.x; j < n; j += blockDim.x) row[j] *= inv;
    for (int j = n + threadIdx.x; j < TDIM; j += blockDim.x) row[j] = 0.f;
}

__device__ __forceinline__ unsigned f2tf(float x) {
    unsigned u;
    asm("cvt.rna.tf32.f32 %0, %1;" : "=r"(u) : "f"(x));
    return u;
}

#define ABUF 4608   // 128*36 floats
#define GEMM_SMEM (4 * ABUF * 4)   // 2 A bufs + 2 B bufs, bytes

// compute one 32-k slab: 8 warps of 32x64, mma.m16n8k8.tf32
template<int TB>
__device__ __forceinline__ void compute_slab(const float* __restrict__ As,
                                             const float* __restrict__ Bs,
                                             float acc[2][8][4],
                                             int wm, int wn, int g, int tg)
{
    #pragma unroll
    for (int kk = 0; kk < 4; kk++) {
        const int kb = kk * 8;
        unsigned af[2][4];
        #pragma unroll
        for (int mt = 0; mt < 2; mt++) {
            int rb = wm * 32 + mt * 16;
            af[mt][0] = f2tf(As[(rb + g) * 36 + kb + tg]);
            af[mt][1] = f2tf(As[(rb + g + 8) * 36 + kb + tg]);
            af[mt][2] = f2tf(As[(rb + g) * 36 + kb + tg + 4]);
            af[mt][3] = f2tf(As[(rb + g + 8) * 36 + kb + tg + 4]);
        }
        unsigned bf[8][2];
        #pragma unroll
        for (int nt = 0; nt < 8; nt++) {
            int col = wn * 64 + nt * 8 + g;
            if (TB == 0) {
                bf[nt][0] = f2tf(Bs[(kb + tg) * 136 + col]);
                bf[nt][1] = f2tf(Bs[(kb + tg + 4) * 136 + col]);
            } else {
                bf[nt][0] = f2tf(Bs[col * 36 + kb + tg]);
                bf[nt][1] = f2tf(Bs[col * 36 + kb + tg + 4]);
            }
        }
        #pragma unroll
        for (int mt = 0; mt < 2; mt++)
            #pragma unroll
            for (int nt = 0; nt < 8; nt++) {
                asm volatile(
                    "mma.sync.aligned.m16n8k8.row.col.f32.tf32.tf32.f32 "
                    "{%0,%1,%2,%3}, {%4,%5,%6,%7}, {%8,%9}, {%0,%1,%2,%3};\n"
                    : "+f"(acc[mt][nt][0]), "+f"(acc[mt][nt][1]),
                      "+f"(acc[mt][nt][2]), "+f"(acc[mt][nt][3])
                    : "r"(af[mt][0]), "r"(af[mt][1]), "r"(af[mt][2]), "r"(af[mt][3]),
                      "r"(bf[nt][0]), "r"(bf[nt][1]));
            }
    }
}

// ---- tf32 tensor-core GEMM, cp.async 2-stage pipeline ----
// TB: 0 -> B is [K,N] row-major; 1 -> B is [N,K] row-major (B^T)
// EP: 0 none, 1 gelu(tanh), 2 add residual
template<int TB, int EP>
__global__ void __launch_bounds__(256, 2)
gemm_tc(const float* __restrict__ A, long long sAb, long long sAh,
        const float* __restrict__ Bm, long long sBb, long long sBh,
        float* __restrict__ C, long long sCb, long long sCh,
        const float* __restrict__ bias,
        const float* __restrict__ res,
        int M, int N, int K, int lda, int ldb, int ldc,
        float alpha, int zdiv)
{
    extern __shared__ float sm[];
    float* AsBuf[2] = { sm,            sm + ABUF };
    float* BsBuf[2] = { sm + 2 * ABUF, sm + 3 * ABUF };

    int z = blockIdx.z;
    int zb = z / zdiv, zh = z % zdiv;
    A  += zb * sAb + zh * sAh;
    Bm += zb * sBb + zh * sBh;
    C  += zb * sCb + zh * sCh;

    const int m0 = blockIdx.y * 128;
    const int n0 = blockIdx.x * 128;
    const int tid = threadIdx.x;
    const int warp = tid >> 5, lane = tid & 31;
    const int g = lane >> 2, tg = lane & 3;
    const int wm = warp >> 1, wn = warp & 1;

    float acc[2][8][4];
    #pragma unroll
    for (int mt = 0; mt < 2; mt++)
        #pragma unroll
        for (int nt = 0; nt < 8; nt++)
            #pragma unroll
            for (int c = 0; c < 4; c++) acc[mt][nt][c] = 0.f;

    // issue cp.async for one 32-k slab into buffer `buf`
    auto issue = [&](int k0, int buf) {
        unsigned a_base = (unsigned)__cvta_generic_to_shared(AsBuf[buf]);
        unsigned b_base = (unsigned)__cvta_generic_to_shared(BsBuf[buf]);
        #pragma unroll
        for (int it = 0; it < 4; it++) {
            int idx = tid + it * 256;
            int row = idx >> 3, c4 = (idx & 7) * 4;
            int gr = m0 + row;
            const float* src = &A[(long long)gr * lda + k0 + c4];
            int sz = (gr < M) ? 16 : 0;
            if (!sz) src = A;
            unsigned dst = a_base + (unsigned)(row * 36 + c4) * 4u;
            asm volatile("cp.async.cg.shared.global [%0], [%1], 16, %2;\n"
                         :: "r"(dst), "l"(src), "r"(sz));
        }
        if (TB == 0) {
            #pragma unroll
            for (int it = 0; it < 4; it++) {
                int idx = tid + it * 256;
                int r = idx >> 5, c4 = (idx & 31) * 4;
                int gc = n0 + c4;
                const float* src = &Bm[(long long)(k0 + r) * ldb + gc];
                int sz = (gc < N) ? 16 : 0;
                if (!sz) src = Bm;
                unsigned dst = b_base + (unsigned)(r * 136 + c4) * 4u;
                asm volatile("cp.async.cg.shared.global [%0], [%1], 16, %2;\n"
                             :: "r"(dst), "l"(src), "r"(sz));
            }
        } else {
            #pragma unroll
            for (int it = 0; it < 4; it++) {
                int idx = tid + it * 256;
                int nn = idx >> 3, kc4 = (idx & 7) * 4;
                int gn = n0 + nn;
                const float* src = &Bm[(long long)gn * ldb + k0 + kc4];
                int sz = (gn < N) ? 16 : 0;
                if (!sz) src = Bm;
                unsigned dst = b_base + (unsigned)(nn * 36 + kc4) * 4u;
                asm volatile("cp.async.cg.shared.global [%0], [%1], 16, %2;\n"
                             :: "r"(dst), "l"(src), "r"(sz));
            }
        }
        asm volatile("cp.async.commit_group;\n" ::: "memory");
    };

    const int S = K >> 5;   // K is always a multiple of 32 here
    issue(0, 0);
    if (S > 1) issue(32, 1);

    for (int s = 0; s < S; s++) {
        if (s + 1 < S) {
            asm volatile("cp.async.wait_group 1;\n" ::: "memory");
        } else {
            asm volatile("cp.async.wait_group 0;\n" ::: "memory");
        }
        __syncthreads();
        compute_slab<TB>(AsBuf[s & 1], BsBuf[s & 1], acc, wm, wn, g, tg);
        __syncthreads();
        if (s + 2 < S) issue((s + 2) << 5, s & 1);
    }

    // ---- epilogue ----
    #pragma unroll
    for (int mt = 0; mt < 2; mt++) {
        #pragma unroll
        for (int nt = 0; nt < 8; nt++) {
            int col = n0 + wn * 64 + nt * 8 + 2 * tg;
            int r0 = m0 + wm * 32 + mt * 16 + g;
            #pragma unroll
            for (int ci = 0; ci < 4; ci++) {
                int r = r0 + (ci >> 1) * 8;
                int c = col + (ci & 1);
                if (r >= M || c >= N) continue;
                float v = alpha * acc[mt][nt][ci];
                if (bias) v += bias[c];
                if (EP == 1) {
                    float u = v;
                    v = 0.5f * u * (1.f + tanhf(0.7978845608028654f * (u + 0.044715f * u * u * u)));
                }
                if (EP == 2) v += res[(long long)r * ldc + c];
                C[(long long)r * ldc + c] = v;
            }
        }
    }
}

extern "C" void kernel_launch(void* const* d_in, const int* in_sizes, int n_in,
                              void* d_out, int out_size) {
    const int*   idx    = (const int*)  d_in[0];
    const float* wte    = (const float*)d_in[1];
    const float* wpe    = (const float*)d_in[2];
    const float* ln1_w  = (const float*)d_in[3];
    const float* ln1_b  = (const float*)d_in[4];
    const float* attn_w = (const float*)d_in[5];
    const float* attn_b = (const float*)d_in[6];
    const float* atp_w  = (const float*)d_in[7];
    const float* atp_b  = (const float*)d_in[8];
    const float* ln2_w  = (const float*)d_in[9];
    const float* ln2_b  = (const float*)d_in[10];
    const float* fc_w   = (const float*)d_in[11];
    const float* fc_b   = (const float*)d_in[12];
    const float* pr_w   = (const float*)d_in[13];
    const float* pr_b   = (const float*)d_in[14];
    const float* lnf_w  = (const float*)d_in[15];
    const float* lnf_b  = (const float*)d_in[16];
    float* out = (float*)d_out;

    float *gx, *gh, *gqkv, *gatt, *gy, *gm;
    cudaGetSymbolAddress((void**)&gx,   g_x);
    cudaGetSymbolAddress((void**)&gh,   g_h);
    cudaGetSymbolAddress((void**)&gqkv, g_qkv);
    cudaGetSymbolAddress((void**)&gatt, g_att);
    cudaGetSymbolAddress((void**)&gy,   g_y);
    cudaGetSymbolAddress((void**)&gm,   g_m);

    // allow 72KB dynamic smem (idempotent)
    cudaFuncSetAttribute(gemm_tc<0,0>, cudaFuncAttributeMaxDynamicSharedMemorySize, GEMM_SMEM);
    cudaFuncSetAttribute(gemm_tc<0,1>, cudaFuncAttributeMaxDynamicSharedMemorySize, GEMM_SMEM);
    cudaFuncSetAttribute(gemm_tc<0,2>, cudaFuncAttributeMaxDynamicSharedMemorySize, GEMM_SMEM);
    cudaFuncSetAttribute(gemm_tc<1,0>, cudaFuncAttributeMaxDynamicSharedMemorySize, GEMM_SMEM);

    const float scale = 0.03608439182435161f;  // 1/sqrt(E)

    embed_kernel<<<BT, 256>>>(idx, wte, wpe);

    for (int l = 0; l < NL; l++) {
        layernorm_kernel<<<BT, 256>>>(gx, gh, ln1_w + l * EDIM, ln1_b + l * EDIM);

        // qkv = h @ attn_w + attn_b
        {
            dim3 g((3 * EDIM + 127) / 128, (BT + 127) / 128, 1);
            gemm_tc<0, 0><<<g, 256, GEMM_SMEM>>>(gh, 0, 0,
                                      attn_w + (long long)l * EDIM * 3 * EDIM, 0, 0,
                                      gqkv, 0, 0,
                                      attn_b + l * 3 * EDIM, nullptr,
                                      BT, 3 * EDIM, EDIM, EDIM, 3 * EDIM, 3 * EDIM,
                                      1.f, 1);
        }
        // scores = scale * Q @ K^T
        {
            dim3 g(TDIM / 128, TDIM / 128, BDIM * NH);
            gemm_tc<1, 0><<<g, 256, GEMM_SMEM>>>(gqkv, (long long)TDIM * 3 * EDIM, HD,
                                      gqkv + EDIM, (long long)TDIM * 3 * EDIM, HD,
                                      gatt, (long long)NH * TDIM * TDIM, (long long)TDIM * TDIM,
                                      nullptr, nullptr,
                                      TDIM, TDIM, HD, 3 * EDIM, 3 * EDIM, TDIM,
                                      scale, NH);
        }
        {
            dim3 g(TDIM, BDIM * NH);
            softmax_kernel<<<g, 128>>>();
        }
        // y = attn @ V
        {
            dim3 g(1, TDIM / 128, BDIM * NH);
            gemm_tc<0, 0><<<g, 256, GEMM_SMEM>>>(gatt, (long long)NH * TDIM * TDIM, (long long)TDIM * TDIM,
                                      gqkv + 2 * EDIM, (long long)TDIM * 3 * EDIM, HD,
                                      gy, (long long)TDIM * EDIM, HD,
                                      nullptr, nullptr,
                                      TDIM, HD, TDIM, TDIM, 3 * EDIM, EDIM,
                                      1.f, NH);
        }
        // x = x + y @ atp_w + atp_b
        {
            dim3 g((EDIM + 127) / 128, (BT + 127) / 128, 1);
            gemm_tc<0, 2><<<g, 256, GEMM_SMEM>>>(gy, 0, 0,
                                      atp_w + (long long)l * EDIM * EDIM, 0, 0,
                                      gx, 0, 0,
                                      atp_b + l * EDIM, gx,
                                      BT, EDIM, EDIM, EDIM, EDIM, EDIM,
                                      1.f, 1);
        }
        layernorm_kernel<<<BT, 256>>>(gx, gh, ln2_w + l * EDIM, ln2_b + l * EDIM);

        // m = gelu(h @ fc_w + fc_b)
        {
            dim3 g((4 * EDIM + 127) / 128, (BT + 127) / 128, 1);
            gemm_tc<0, 1><<<g, 256, GEMM_SMEM>>>(gh, 0, 0,
                                      fc_w + (long long)l * EDIM * 4 * EDIM, 0, 0,
                                      gm, 0, 0,
                                      fc_b + l * 4 * EDIM, nullptr,
                                      BT, 4 * EDIM, EDIM, EDIM, 4 * EDIM, 4 * EDIM,
                                      1.f, 1);
        }
        // x = x + m @ pr_w + pr_b
        {
            dim3 g((EDIM + 127) / 128, (BT + 127) / 128, 1);
            gemm_tc<0, 2><<<g, 256, GEMM_SMEM>>>(gm, 0, 0,
                                      pr_w + (long long)l * 4 * EDIM * EDIM, 0, 0,
                                      gx, 0, 0,
                                      pr_b + l * EDIM, gx,
                                      BT, EDIM, 4 * EDIM, 4 * EDIM, EDIM, EDIM,
                                      1.f, 1);
        }
    }

    layernorm_kernel<<<BT, 256>>>(gx, gh, lnf_w, lnf_b);

    // logits = h @ wte^T
    {
        dim3 g((VDIM + 127) / 128, (BT + 127) / 128, 1);
        gemm_tc<1, 0><<<g, 256, GEMM_SMEM>>>(gh, 0, 0,
                                  wte, 0, 0,
                                  out, 0, 0,
                                  nullptr, nullptr,
                                  BT, VDIM, EDIM, EDIM, EDIM, VDIM,
                                  1.f, 1);
    }
}

// round 4
// speedup vs baseline: 3.0891x; 1.1443x over previous
#include <cuda_runtime.h>
#include <math.h>

// Problem constants (GPT_5875515261622)
#define NL   4
#define NH   12
#define EDIM 768
#define TDIM 1024
#define BDIM 2
#define VDIM 50257
#define HD   64
#define BT   (BDIM*TDIM)

// ---- scratch (device globals; no runtime allocation allowed) ----
__device__ float g_x  [BT*EDIM];
__device__ float g_h  [BT*EDIM];
__device__ float g_qkv[BT*3*EDIM];
__device__ float g_att[(long long)BDIM*NH*TDIM*TDIM];
__device__ float g_y  [BT*EDIM];
__device__ float g_m  [BT*4*EDIM];

// tf32-rounded weight copies
__device__ float c_attn_w[NL*EDIM*3*EDIM];
__device__ float c_atp_w [NL*EDIM*EDIM];
__device__ float c_fc_w  [NL*EDIM*4*EDIM];
__device__ float c_pr_w  [NL*4*EDIM*EDIM];
__device__ float c_wte   [(long long)VDIM*EDIM];

__device__ __forceinline__ float rtf(float x) {
    unsigned u;
    asm("cvt.rna.tf32.f32 %0, %1;" : "=r"(u) : "f"(x));
    return __uint_as_float(u);
}

// ---- tf32 rounding prepass (float4 grid-stride) ----
__global__ void tf32_round4(const float4* __restrict__ in, float4* __restrict__ out, int n4) {
    for (int i = blockIdx.x * blockDim.x + threadIdx.x; i < n4; i += gridDim.x * blockDim.x) {
        float4 v = in[i];
        v.x = rtf(v.x); v.y = rtf(v.y); v.z = rtf(v.z); v.w = rtf(v.w);
        out[i] = v;
    }
}

// ---- embedding: x = wte[idx] + wpe[t] ----
__global__ void embed_kernel(const int* __restrict__ idx,
                             const float* __restrict__ wte,
                             const float* __restrict__ wpe) {
    int row = blockIdx.x;
    int t   = row % TDIM;
    long long tok = idx[row];
    const float* src = wte + tok * EDIM;
    const float* pos = wpe + (long long)t * EDIM;
    float* dst = g_x + (long long)row * EDIM;
    for (int c = threadIdx.x; c < EDIM; c += blockDim.x)
        dst[c] = src[c] + pos[c];
}

// ---- layernorm (rounds output to tf32; output feeds GEMMs only) ----
__global__ void layernorm_kernel(const float* __restrict__ in,
                                 float* __restrict__ out,
                                 const float* __restrict__ w,
                                 const float* __restrict__ b) {
    int row = blockIdx.x;
    const float* x = in + (long long)row * EDIM;
    float* o = out + (long long)row * EDIM;
    __shared__ float red[256];
    float s = 0.f;
    for (int c = threadIdx.x; c < EDIM; c += blockDim.x) s += x[c];
    red[threadIdx.x] = s; __syncthreads();
    for (int st = 128; st > 0; st >>= 1) {
        if (threadIdx.x < st) red[threadIdx.x] += red[threadIdx.x + st];
        __syncthreads();
    }
    float mu = red[0] * (1.f / EDIM);
    __syncthreads();
    float v = 0.f;
    for (int c = threadIdx.x; c < EDIM; c += blockDim.x) { float d = x[c] - mu; v += d * d; }
    red[threadIdx.x] = v; __syncthreads();
    for (int st = 128; st > 0; st >>= 1) {
        if (threadIdx.x < st) red[threadIdx.x] += red[threadIdx.x + st];
        __syncthreads();
    }
    float rstd = rsqrtf(red[0] * (1.f / EDIM) + 1e-5f);
    for (int c = threadIdx.x; c < EDIM; c += blockDim.x)
        o[c] = rtf((x[c] - mu) * rstd * w[c] + b[c]);
}

// ---- final layernorm variant without rounding? (not needed; logits GEMM rounds A) ----

// ---- causal softmax (rounds output; feeds AV GEMM only) ----
__global__ void softmax_kernel() {
    int i = blockIdx.x;
    long long z = blockIdx.y;
    float* row = g_att + (z * TDIM + i) * (long long)TDIM;
    int n = i + 1;
    __shared__ float red[128];
    float mx = -1e30f;
    for (int j = threadIdx.x; j < n; j += blockDim.x) mx = fmaxf(mx, row[j]);
    red[threadIdx.x] = mx; __syncthreads();
    for (int st = 64; st > 0; st >>= 1) {
        if (threadIdx.x < st) red[threadIdx.x] = fmaxf(red[threadIdx.x], red[threadIdx.x + st]);
        __syncthreads();
    }
    mx = red[0]; __syncthreads();
    float s = 0.f;
    for (int j = threadIdx.x; j < n; j += blockDim.x) { float e = __expf(row[j] - mx); row[j] = e; s += e; }
    red[threadIdx.x] = s; __syncthreads();
    for (int st = 64; st > 0; st >>= 1) {
        if (threadIdx.x < st) red[threadIdx.x] += red[threadIdx.x + st];
        __syncthreads();
    }
    float inv = 1.f / red[0];
    for (int j = threadIdx.x; j < n; j += blockDim.x) row[j] = rtf(row[j] * inv);
    for (int j = n + threadIdx.x; j < TDIM; j += blockDim.x) row[j] = 0.f;
}

#define ABUF 4608   // 128*36 floats
#define GEMM_SMEM (4 * ABUF * 4)   // 2 A bufs + 2 B bufs, bytes

// compute one 32-k slab. Operands in smem are pre-rounded tf32 -> no cvt.
// NTF: B-fragments per warp (CTA N width = 16*NTF). Warp tile 32 x (8*NTF).
template<int TB, int NTF>
__device__ __forceinline__ void compute_slab(const float* __restrict__ As,
                                             const float* __restrict__ Bs,
                                             float acc[2][NTF][4],
                                             int wm, int wn, int g, int tg)
{
    const int LDB = 16 * NTF + 8;
    #pragma unroll
    for (int kk = 0; kk < 4; kk++) {
        const int kb = kk * 8;
        unsigned af[2][4];
        #pragma unroll
        for (int mt = 0; mt < 2; mt++) {
            int rb = wm * 32 + mt * 16;
            af[mt][0] = __float_as_uint(As[(rb + g) * 36 + kb + tg]);
            af[mt][1] = __float_as_uint(As[(rb + g + 8) * 36 + kb + tg]);
            af[mt][2] = __float_as_uint(As[(rb + g) * 36 + kb + tg + 4]);
            af[mt][3] = __float_as_uint(As[(rb + g + 8) * 36 + kb + tg + 4]);
        }
        unsigned bf[NTF][2];
        #pragma unroll
        for (int nt = 0; nt < NTF; nt++) {
            int col = wn * (8 * NTF) + nt * 8 + g;
            if (TB == 0) {
                bf[nt][0] = __float_as_uint(Bs[(kb + tg) * LDB + col]);
                bf[nt][1] = __float_as_uint(Bs[(kb + tg + 4) * LDB + col]);
            } else {
                bf[nt][0] = __float_as_uint(Bs[col * 36 + kb + tg]);
                bf[nt][1] = __float_as_uint(Bs[col * 36 + kb + tg + 4]);
            }
        }
        #pragma unroll
        for (int mt = 0; mt < 2; mt++)
            #pragma unroll
            for (int nt = 0; nt < NTF; nt++) {
                asm volatile(
                    "mma.sync.aligned.m16n8k8.row.col.f32.tf32.tf32.f32 "
                    "{%0,%1,%2,%3}, {%4,%5,%6,%7}, {%8,%9}, {%0,%1,%2,%3};\n"
                    : "+f"(acc[mt][nt][0]), "+f"(acc[mt][nt][1]),
                      "+f"(acc[mt][nt][2]), "+f"(acc[mt][nt][3])
                    : "r"(af[mt][0]), "r"(af[mt][1]), "r"(af[mt][2]), "r"(af[mt][3]),
                      "r"(bf[nt][0]), "r"(bf[nt][1]));
            }
    }
}

// ---- tf32 tensor-core GEMM, cp.async 2-stage pipeline, pre-rounded operands ----
// TB: 0 -> B is [K,N] row-major; 1 -> B is [N,K] row-major (B^T)
// EP: 0 none, 1 gelu(tanh), 2 add residual
// NTF: CTA N width = 16*NTF (8 -> 128, 4 -> 64)
template<int TB, int EP, int NTF>
__global__ void __launch_bounds__(256, 2)
gemm_tc(const float* __restrict__ A, long long sAb, long long sAh,
        const float* __restrict__ Bm, long long sBb, long long sBh,
        float* __restrict__ C, long long sCb, long long sCh,
        const float* __restrict__ bias,
        const float* __restrict__ res,
        int M, int N, int K, int lda, int ldb, int ldc,
        float alpha, int zdiv, int rnd, int causal)
{
    extern __shared__ float sm[];
    float* AsBuf[2] = { sm,            sm + ABUF };
    float* BsBuf[2] = { sm + 2 * ABUF, sm + 3 * ABUF };

    const int m0 = blockIdx.y * 128;
    const int n0 = blockIdx.x * (16 * NTF);
    if (causal && n0 >= m0 + 128) return;   // fully masked QK^T tile

    int z = blockIdx.z;
    int zb = z / zdiv, zh = z % zdiv;
    A  += zb * sAb + zh * sAh;
    Bm += zb * sBb + zh * sBh;
    C  += zb * sCb + zh * sCh;

    const int tid = threadIdx.x;
    const int warp = tid >> 5, lane = tid & 31;
    const int g = lane >> 2, tg = lane & 3;
    const int wm = warp >> 1, wn = warp & 1;
    const int LDB = 16 * NTF + 8;

    float acc[2][NTF][4];
    #pragma unroll
    for (int mt = 0; mt < 2; mt++)
        #pragma unroll
        for (int nt = 0; nt < NTF; nt++)
            #pragma unroll
            for (int c = 0; c < 4; c++) acc[mt][nt][c] = 0.f;

    auto issue = [&](int k0, int buf) {
        unsigned a_base = (unsigned)__cvta_generic_to_shared(AsBuf[buf]);
        unsigned b_base = (unsigned)__cvta_generic_to_shared(BsBuf[buf]);
        #pragma unroll
        for (int it = 0; it < 4; it++) {
            int idx = tid + it * 256;
            int row = idx >> 3, c4 = (idx & 7) * 4;
            int gr = m0 + row;
            const float* src = &A[(long long)gr * lda + k0 + c4];
            int sz = (gr < M) ? 16 : 0;
            if (!sz) src = A;
            unsigned dst = a_base + (unsigned)(row * 36 + c4) * 4u;
            asm volatile("cp.async.cg.shared.global [%0], [%1], 16, %2;\n"
                         :: "r"(dst), "l"(src), "r"(sz));
        }
        if (TB == 0) {
            #pragma unroll
            for (int it = 0; it < NTF / 2; it++) {
                int idx = tid + it * 256;
                int r = idx / (4 * NTF), c4 = (idx % (4 * NTF)) * 4;
                int gc = n0 + c4;
                const float* src = &Bm[(long long)(k0 + r) * ldb + gc];
                int sz = (gc < N) ? 16 : 0;
                if (!sz) src = Bm;
                unsigned dst = b_base + (unsigned)(r * LDB + c4) * 4u;
                asm volatile("cp.async.cg.shared.global [%0], [%1], 16, %2;\n"
                             :: "r"(dst), "l"(src), "r"(sz));
            }
        } else {
            #pragma unroll
            for (int it = 0; it < 4; it++) {
                int idx = tid + it * 256;
                int nn = idx >> 3, kc4 = (idx & 7) * 4;
                int gn = n0 + nn;
                const float* src = &Bm[(long long)gn * ldb + k0 + kc4];
                int sz = (gn < N) ? 16 : 0;
                if (!sz) src = Bm;
                unsigned dst = b_base + (unsigned)(nn * 36 + kc4) * 4u;
                asm volatile("cp.async.cg.shared.global [%0], [%1], 16, %2;\n"
                             :: "r"(dst), "l"(src), "r"(sz));
            }
        }
        asm volatile("cp.async.commit_group;\n" ::: "memory");
    };

    const int S = K >> 5;
    issue(0, 0);
    if (S > 1) issue(32, 1);

    for (int s = 0; s < S; s++) {
        if (s + 1 < S) {
            asm volatile("cp.async.wait_group 1;\n" ::: "memory");
        } else {
            asm volatile("cp.async.wait_group 0;\n" ::: "memory");
        }
        __syncthreads();
        compute_slab<TB, NTF>(AsBuf[s & 1], BsBuf[s & 1], acc, wm, wn, g, tg);
        __syncthreads();
        if (s + 2 < S) issue((s + 2) << 5, s & 1);
    }

    // ---- epilogue ----
    #pragma unroll
    for (int mt = 0; mt < 2; mt++) {
        #pragma unroll
        for (int nt = 0; nt < NTF; nt++) {
            int col = n0 + wn * (8 * NTF) + nt * 8 + 2 * tg;
            int r0 = m0 + wm * 32 + mt * 16 + g;
            #pragma unroll
            for (int ci = 0; ci < 4; ci++) {
                int r = r0 + (ci >> 1) * 8;
                int c = col + (ci & 1);
                if (r >= M || c >= N) continue;
                float v = alpha * acc[mt][nt][ci];
                if (bias) v += bias[c];
                if (EP == 1) {
                    float u = v;
                    v = 0.5f * u * (1.f + tanhf(0.7978845608028654f * (u + 0.044715f * u * u * u)));
                }
                if (EP == 2) v += res[(long long)r * ldc + c];
                if (rnd) v = rtf(v);
                C[(long long)r * ldc + c] = v;
            }
        }
    }
}

extern "C" void kernel_launch(void* const* d_in, const int* in_sizes, int n_in,
                              void* d_out, int out_size) {
    const int*   idx    = (const int*)  d_in[0];
    const float* wte    = (const float*)d_in[1];
    const float* wpe    = (const float*)d_in[2];
    const float* ln1_w  = (const float*)d_in[3];
    const float* ln1_b  = (const float*)d_in[4];
    const float* attn_w = (const float*)d_in[5];
    const float* attn_b = (const float*)d_in[6];
    const float* atp_w  = (const float*)d_in[7];
    const float* atp_b  = (const float*)d_in[8];
    const float* ln2_w  = (const float*)d_in[9];
    const float* ln2_b  = (const float*)d_in[10];
    const float* fc_w   = (const float*)d_in[11];
    const float* fc_b   = (const float*)d_in[12];
    const float* pr_w   = (const float*)d_in[13];
    const float* pr_b   = (const float*)d_in[14];
    const float* lnf_w  = (const float*)d_in[15];
    const float* lnf_b  = (const float*)d_in[16];
    float* out = (float*)d_out;

    float *gx, *gh, *gqkv, *gatt, *gy, *gm;
    float *cw_attn, *cw_atp, *cw_fc, *cw_pr, *cw_wte;
    cudaGetSymbolAddress((void**)&gx,   g_x);
    cudaGetSymbolAddress((void**)&gh,   g_h);
    cudaGetSymbolAddress((void**)&gqkv, g_qkv);
    cudaGetSymbolAddress((void**)&gatt, g_att);
    cudaGetSymbolAddress((void**)&gy,   g_y);
    cudaGetSymbolAddress((void**)&gm,   g_m);
    cudaGetSymbolAddress((void**)&cw_attn, c_attn_w);
    cudaGetSymbolAddress((void**)&cw_atp,  c_atp_w);
    cudaGetSymbolAddress((void**)&cw_fc,   c_fc_w);
    cudaGetSymbolAddress((void**)&cw_pr,   c_pr_w);
    cudaGetSymbolAddress((void**)&cw_wte,  c_wte);

    cudaFuncSetAttribute(gemm_tc<0,0,8>, cudaFuncAttributeMaxDynamicSharedMemorySize, GEMM_SMEM);
    cudaFuncSetAttribute(gemm_tc<0,1,8>, cudaFuncAttributeMaxDynamicSharedMemorySize, GEMM_SMEM);
    cudaFuncSetAttribute(gemm_tc<0,2,8>, cudaFuncAttributeMaxDynamicSharedMemorySize, GEMM_SMEM);
    cudaFuncSetAttribute(gemm_tc<1,0,8>, cudaFuncAttributeMaxDynamicSharedMemorySize, GEMM_SMEM);
    cudaFuncSetAttribute(gemm_tc<0,0,4>, cudaFuncAttributeMaxDynamicSharedMemorySize, GEMM_SMEM);

    const float scale = 0.03608439182435161f;  // 1/sqrt(E)

    // ---- weight tf32 prepass ----
    tf32_round4<<<4096, 256>>>((const float4*)attn_w, (float4*)cw_attn, NL*EDIM*3*EDIM/4);
    tf32_round4<<<4096, 256>>>((const float4*)atp_w,  (float4*)cw_atp,  NL*EDIM*EDIM/4);
    tf32_round4<<<4096, 256>>>((const float4*)fc_w,   (float4*)cw_fc,   NL*EDIM*4*EDIM/4);
    tf32_round4<<<4096, 256>>>((const float4*)pr_w,   (float4*)cw_pr,   NL*4*EDIM*EDIM/4);
    tf32_round4<<<8192, 256>>>((const float4*)wte,    (float4*)cw_wte,  VDIM*EDIM/4);

    embed_kernel<<<BT, 256>>>(idx, wte, wpe);

    for (int l = 0; l < NL; l++) {
        layernorm_kernel<<<BT, 256>>>(gx, gh, ln1_w + l * EDIM, ln1_b + l * EDIM);

        // qkv = h @ attn_w + attn_b  (rounded out)
        {
            dim3 g((3 * EDIM + 127) / 128, (BT + 127) / 128, 1);
            gemm_tc<0, 0, 8><<<g, 256, GEMM_SMEM>>>(gh, 0, 0,
                                      cw_attn + (long long)l * EDIM * 3 * EDIM, 0, 0,
                                      gqkv, 0, 0,
                                      attn_b + l * 3 * EDIM, nullptr,
                                      BT, 3 * EDIM, EDIM, EDIM, 3 * EDIM, 3 * EDIM,
                                      1.f, 1, 1, 0);
        }
        // scores = scale * Q @ K^T  (causal skip; softmax rounds)
        {
            dim3 g(TDIM / 128, TDIM / 128, BDIM * NH);
            gemm_tc<1, 0, 8><<<g, 256, GEMM_SMEM>>>(gqkv, (long long)TDIM * 3 * EDIM, HD,
                                      gqkv + EDIM, (long long)TDIM * 3 * EDIM, HD,
                                      gatt, (long long)NH * TDIM * TDIM, (long long)TDIM * TDIM,
                                      nullptr, nullptr,
                                      TDIM, TDIM, HD, 3 * EDIM, 3 * EDIM, TDIM,
                                      scale, NH, 0, 1);
        }
        {
            dim3 g(TDIM, BDIM * NH);
            softmax_kernel<<<g, 128>>>();
        }
        // y = attn @ V  (N=64 tile; rounded out)
        {
            dim3 g(1, TDIM / 128, BDIM * NH);
            gemm_tc<0, 0, 4><<<g, 256, GEMM_SMEM>>>(gatt, (long long)NH * TDIM * TDIM, (long long)TDIM * TDIM,
                                      gqkv + 2 * EDIM, (long long)TDIM * 3 * EDIM, HD,
                                      gy, (long long)TDIM * EDIM, HD,
                                      nullptr, nullptr,
                                      TDIM, HD, TDIM, TDIM, 3 * EDIM, EDIM,
                                      1.f, NH, 1, 0);
        }
        // x = x + y @ atp_w + atp_b
        {
            dim3 g((EDIM + 127) / 128, (BT + 127) / 128, 1);
            gemm_tc<0, 2, 8><<<g, 256, GEMM_SMEM>>>(gy, 0, 0,
                                      cw_atp + (long long)l * EDIM * EDIM, 0, 0,
                                      gx, 0, 0,
                                      atp_b + l * EDIM, gx,
                                      BT, EDIM, EDIM, EDIM, EDIM, EDIM,
                                      1.f, 1, 0, 0);
        }
        layernorm_kernel<<<BT, 256>>>(gx, gh, ln2_w + l * EDIM, ln2_b + l * EDIM);

        // m = gelu(h @ fc_w + fc_b)  (rounded out)
        {
            dim3 g((4 * EDIM + 127) / 128, (BT + 127) / 128, 1);
            gemm_tc<0, 1, 8><<<g, 256, GEMM_SMEM>>>(gh, 0, 0,
                                      cw_fc + (long long)l * EDIM * 4 * EDIM, 0, 0,
                                      gm, 0, 0,
                                      fc_b + l * 4 * EDIM, nullptr,
                                      BT, 4 * EDIM, EDIM, EDIM, 4 * EDIM, 4 * EDIM,
                                      1.f, 1, 1, 0);
        }
        // x = x + m @ pr_w + pr_b
        {
            dim3 g((EDIM + 127) / 128, (BT + 127) / 128, 1);
            gemm_tc<0, 2, 8><<<g, 256, GEMM_SMEM>>>(gm, 0, 0,
                                      cw_pr + (long long)l * 4 * EDIM * EDIM, 0, 0,
                                      gx, 0, 0,
                                      pr_b + l * EDIM, gx,
                                      BT, EDIM, 4 * EDIM, 4 * EDIM, EDIM, EDIM,
                                      1.f, 1, 0, 0);
        }
    }

    layernorm_kernel<<<BT, 256>>>(gx, gh, lnf_w, lnf_b);

    // logits = h @ wte^T
    {
        dim3 g((VDIM + 127) / 128, (BT + 127) / 128, 1);
        gemm_tc<1, 0, 8><<<g, 256, GEMM_SMEM>>>(gh, 0, 0,
                                  cw_wte, 0, 0,
                                  out, 0, 0,
                                  nullptr, nullptr,
                                  BT, VDIM, EDIM, EDIM, EDIM, VDIM,
                                  1.f, 1, 0, 0);
    }
}

// round 5
// speedup vs baseline: 3.3188x; 1.0744x over previous
#include <cuda_runtime.h>
#include <math.h>

// Problem constants (GPT_5875515261622)
#define NL   4
#define NH   12
#define EDIM 768
#define TDIM 1024
#define BDIM 2
#define VDIM 50257
#define HD   64
#define BT   (BDIM*TDIM)

// ---- scratch (device globals; no runtime allocation allowed) ----
__device__ float g_x  [BT*EDIM];
__device__ float g_h  [BT*EDIM];
__device__ float g_qkv[BT*3*EDIM];
__device__ float g_att[(long long)BDIM*NH*TDIM*TDIM];
__device__ float g_y  [BT*EDIM];
__device__ float g_m  [BT*4*EDIM];
__device__ float g_vt [BDIM*NH*HD*TDIM];   // V transposed per (b,h): [d][t]

// tf32-rounded, transposed ([out][in] n-major) weight copies
__device__ float c_attn_w[NL*EDIM*3*EDIM];
__device__ float c_atp_w [NL*EDIM*EDIM];
__device__ float c_fc_w  [NL*EDIM*4*EDIM];
__device__ float c_pr_w  [NL*4*EDIM*EDIM];
__device__ float c_wte   [(long long)VDIM*EDIM];   // round only (already n-major)

__device__ __forceinline__ float rtf(float x) {
    unsigned u;
    asm("cvt.rna.tf32.f32 %0, %1;" : "=r"(u) : "f"(x));
    return __uint_as_float(u);
}

// ---- tf32 rounding prepass (float4 grid-stride) ----
__global__ void tf32_round4(const float4* __restrict__ in, float4* __restrict__ out, int n4) {
    for (int i = blockIdx.x * blockDim.x + threadIdx.x; i < n4; i += gridDim.x * blockDim.x) {
        float4 v = in[i];
        v.x = rtf(v.x); v.y = rtf(v.y); v.z = rtf(v.z); v.w = rtf(v.w);
        out[i] = v;
    }
}

// ---- transpose + tf32 round: in [K][N] row-major -> out [N][K] row-major ----
// grid (N/32, K/32, L), block (32, 8)
__global__ void transpose_round(const float* __restrict__ in, float* __restrict__ out,
                                int K, int N) {
    __shared__ float t[32][33];
    long long zoff = (long long)blockIdx.z * K * N;
    in += zoff; out += zoff;
    int n0 = blockIdx.x * 32, k0 = blockIdx.y * 32;
    int x = threadIdx.x, y = threadIdx.y;
    #pragma unroll
    for (int i = y; i < 32; i += 8)
        t[i][x] = rtf(in[(long long)(k0 + i) * N + n0 + x]);
    __syncthreads();
    #pragma unroll
    for (int i = y; i < 32; i += 8)
        out[(long long)(n0 + i) * K + k0 + x] = t[x][i];
}

// ---- V transpose: gqkv V-slice [t][d] -> g_vt[(b*NH+h)][d][t] ----
// grid (T/32, HD/32, B*NH), block (32, 8)
__global__ void v_transpose() {
    __shared__ float t[32][33];
    int z = blockIdx.z;
    int b = z / NH, h = z % NH;
    int t0 = blockIdx.x * 32, d0 = blockIdx.y * 32;
    int x = threadIdx.x, y = threadIdx.y;
    #pragma unroll
    for (int i = y; i < 32; i += 8)
        t[i][x] = g_qkv[((long long)(b * TDIM + t0 + i)) * (3 * EDIM) + 2 * EDIM + h * HD + d0 + x];
    __syncthreads();
    #pragma unroll
    for (int i = y; i < 32; i += 8)
        g_vt[((long long)z * HD + d0 + i) * TDIM + t0 + x] = t[x][i];
}

// ---- embedding: x = wte[idx] + wpe[t] ----
__global__ void embed_kernel(const int* __restrict__ idx,
                             const float* __restrict__ wte,
                             const float* __restrict__ wpe) {
    int row = blockIdx.x;
    int t   = row % TDIM;
    long long tok = idx[row];
    const float* src = wte + tok * EDIM;
    const float* pos = wpe + (long long)t * EDIM;
    float* dst = g_x + (long long)row * EDIM;
    for (int c = threadIdx.x; c < EDIM; c += blockDim.x)
        dst[c] = src[c] + pos[c];
}

// ---- layernorm (rounds output to tf32; output feeds GEMMs only) ----
__global__ void layernorm_kernel(const float* __restrict__ in,
                                 float* __restrict__ out,
                                 const float* __restrict__ w,
                                 const float* __restrict__ b) {
    int row = blockIdx.x;
    const float* x = in + (long long)row * EDIM;
    float* o = out + (long long)row * EDIM;
    __shared__ float red[256];
    float s = 0.f;
    for (int c = threadIdx.x; c < EDIM; c += blockDim.x) s += x[c];
    red[threadIdx.x] = s; __syncthreads();
    for (int st = 128; st > 0; st >>= 1) {
        if (threadIdx.x < st) red[threadIdx.x] += red[threadIdx.x + st];
        __syncthreads();
    }
    float mu = red[0] * (1.f / EDIM);
    __syncthreads();
    float v = 0.f;
    for (int c = threadIdx.x; c < EDIM; c += blockDim.x) { float d = x[c] - mu; v += d * d; }
    red[threadIdx.x] = v; __syncthreads();
    for (int st = 128; st > 0; st >>= 1) {
        if (threadIdx.x < st) red[threadIdx.x] += red[threadIdx.x + st];
        __syncthreads();
    }
    float rstd = rsqrtf(red[0] * (1.f / EDIM) + 1e-5f);
    for (int c = threadIdx.x; c < EDIM; c += blockDim.x)
        o[c] = rtf((x[c] - mu) * rstd * w[c] + b[c]);
}

// ---- causal softmax (rounds output; zeros masked tail) ----
__global__ void softmax_kernel() {
    int i = blockIdx.x;
    long long z = blockIdx.y;
    float* row = g_att + (z * TDIM + i) * (long long)TDIM;
    int n = i + 1;
    __shared__ float red[128];
    float mx = -1e30f;
    for (int j = threadIdx.x; j < n; j += blockDim.x) mx = fmaxf(mx, row[j]);
    red[threadIdx.x] = mx; __syncthreads();
    for (int st = 64; st > 0; st >>= 1) {
        if (threadIdx.x < st) red[threadIdx.x] = fmaxf(red[threadIdx.x], red[threadIdx.x + st]);
        __syncthreads();
    }
    mx = red[0]; __syncthreads();
    float s = 0.f;
    for (int j = threadIdx.x; j < n; j += blockDim.x) { float e = __expf(row[j] - mx); row[j] = e; s += e; }
    red[threadIdx.x] = s; __syncthreads();
    for (int st = 64; st > 0; st >>= 1) {
        if (threadIdx.x < st) red[threadIdx.x] += red[threadIdx.x + st];
        __syncthreads();
    }
    float inv = 1.f / red[0];
    for (int j = threadIdx.x; j < n; j += blockDim.x) row[j] = rtf(row[j] * inv);
    for (int j = n + threadIdx.x; j < TDIM; j += blockDim.x) row[j] = 0.f;
}

#define ABUF 4608   // 128*36 floats per A stage

// ---- tf32 tensor-core GEMM (all operands pre-rounded tf32) ----
// A: [M][K] row-major (lda = k-stride). B: [N][K] row-major n-major (ldb = k-stride).
// CTA tile 128m x (32*NT16)n, 4 warps (2x2) of 64m x (16*NT16)n, mma.m16n8k8.tf32.
// Fragments via ldmatrix.m8n8.x4.b16. 2-stage cp.async pipeline.
// EP: 0 none, 1 gelu(tanh), 2 add residual
template<int NT16, int EP>
__global__ void __launch_bounds__(128, NT16 == 4 ? 2 : 3)
gemm_tc(const float* __restrict__ A, long long sAb, long long sAh,
        const float* __restrict__ Bm, long long sBb, long long sBh,
        float* __restrict__ C, long long sCb, long long sCh,
        const float* __restrict__ bias,
        const float* __restrict__ res,
        int M, int N, int K, int lda, int ldb, int ldc,
        float alpha, int zdiv, int rnd, int causal)
{
    extern __shared__ float sm[];
    const int BROWS = 32 * NT16;
    float* AsB[2] = { sm, sm + ABUF };
    float* BsB[2] = { sm + 2 * ABUF, sm + 2 * ABUF + BROWS * 36 };

    const int m0 = blockIdx.y * 128;
    const int n0 = blockIdx.x * BROWS;
    if (causal && n0 >= m0 + 128) return;   // fully masked QK^T tile

    int z = blockIdx.z;
    int zb = z / zdiv, zh = z % zdiv;
    A  += zb * sAb + zh * sAh;
    Bm += zb * sBb + zh * sBh;
    C  += zb * sCb + zh * sCh;

    const int tid = threadIdx.x;
    const int warp = tid >> 5, lane = tid & 31;
    const int g = lane >> 2, tg = lane & 3;
    const int wm = warp >> 1, wn = warp & 1;
    const int row_sel = lane & 7, quad = lane >> 3;

    float acc[4][2 * NT16][4];
    #pragma unroll
    for (int mt = 0; mt < 4; mt++)
        #pragma unroll
        for (int nt = 0; nt < 2 * NT16; nt++)
            #pragma unroll
            for (int c = 0; c < 4; c++) acc[mt][nt][c] = 0.f;

    // per-lane ldmatrix row-address offsets (bytes), kb=0
    unsigned aoff[4], boff[NT16];
    #pragma unroll
    for (int mt = 0; mt < 4; mt++)
        aoff[mt] = (unsigned)(((wm * 64 + mt * 16 + (quad & 1) * 8 + row_sel) * 36
                               + (quad >> 1) * 4) * 4);
    #pragma unroll
    for (int p = 0; p < NT16; p++)
        boff[p] = (unsigned)(((wn * 16 * NT16 + p * 16 + (quad >> 1) * 8 + row_sel) * 36
                              + (quad & 1) * 4) * 4);

    unsigned sA[2] = { (unsigned)__cvta_generic_to_shared(AsB[0]),
                       (unsigned)__cvta_generic_to_shared(AsB[1]) };
    unsigned sB[2] = { (unsigned)__cvta_generic_to_shared(BsB[0]),
                       (unsigned)__cvta_generic_to_shared(BsB[1]) };

    auto issue = [&](int k0, int buf) {
        unsigned a_base = sA[buf], b_base = sB[buf];
        #pragma unroll
        for (int it = 0; it < 8; it++) {
            int idx = tid + it * 128;
            int row = idx >> 3, c4 = (idx & 7) * 4;
            int gr = m0 + row;
            const float* src = &A[(long long)gr * lda + k0 + c4];
            int sz = (gr < M) ? 16 : 0;
            if (!sz) src = A;
            unsigned dst = a_base + (unsigned)(row * 36 + c4) * 4u;
            asm volatile("cp.async.cg.shared.global [%0], [%1], 16, %2;\n"
                         :: "r"(dst), "l"(src), "r"(sz));
        }
        #pragma unroll
        for (int it = 0; it < 2 * NT16; it++) {
            int idx = tid + it * 128;
            int nn = idx >> 3, c4 = (idx & 7) * 4;
            int gn = n0 + nn;
            const float* src = &Bm[(long long)gn * ldb + k0 + c4];
            int sz = (gn < N) ? 16 : 0;
            if (!sz) src = Bm;
            unsigned dst = b_base + (unsigned)(nn * 36 + c4) * 4u;
            asm volatile("cp.async.cg.shared.global [%0], [%1], 16, %2;\n"
                         :: "r"(dst), "l"(src), "r"(sz));
        }
        asm volatile("cp.async.commit_group;\n" ::: "memory");
    };

    const int S = K >> 5;
    issue(0, 0);
    if (S > 1) issue(32, 1);

    for (int s = 0; s < S; s++) {
        if (s + 1 < S) {
            asm volatile("cp.async.wait_group 1;\n" ::: "memory");
        } else {
            asm volatile("cp.async.wait_group 0;\n" ::: "memory");
        }
        __syncthreads();
        unsigned abase = sA[s & 1], bbase = sB[s & 1];
        #pragma unroll
        for (int kk = 0; kk < 4; kk++) {
            unsigned af[4][4];
            #pragma unroll
            for (int mt = 0; mt < 4; mt++) {
                asm volatile("ldmatrix.sync.aligned.m8n8.x4.shared.b16 {%0,%1,%2,%3}, [%4];"
                             : "=r"(af[mt][0]), "=r"(af[mt][1]), "=r"(af[mt][2]), "=r"(af[mt][3])
                             : "r"(abase + aoff[mt] + (unsigned)(kk * 32)));
            }
            unsigned bf[2 * NT16][2];
            #pragma unroll
            for (int p = 0; p < NT16; p++) {
                unsigned r0, r1, r2, r3;
                asm volatile("ldmatrix.sync.aligned.m8n8.x4.shared.b16 {%0,%1,%2,%3}, [%4];"
                             : "=r"(r0), "=r"(r1), "=r"(r2), "=r"(r3)
                             : "r"(bbase + boff[p] + (unsigned)(kk * 32)));
                bf[2 * p][0] = r0; bf[2 * p][1] = r1;
                bf[2 * p + 1][0] = r2; bf[2 * p + 1][1] = r3;
            }
            #pragma unroll
            for (int mt = 0; mt < 4; mt++)
                #pragma unroll
                for (int nt = 0; nt < 2 * NT16; nt++) {
                    asm volatile(
                        "mma.sync.aligned.m16n8k8.row.col.f32.tf32.tf32.f32 "
                        "{%0,%1,%2,%3}, {%4,%5,%6,%7}, {%8,%9}, {%0,%1,%2,%3};\n"
                        : "+f"(acc[mt][nt][0]), "+f"(acc[mt][nt][1]),
                          "+f"(acc[mt][nt][2]), "+f"(acc[mt][nt][3])
                        : "r"(af[mt][0]), "r"(af[mt][1]), "r"(af[mt][2]), "r"(af[mt][3]),
                          "r"(bf[nt][0]), "r"(bf[nt][1]));
                }
        }
        __syncthreads();
        if (s + 2 < S) issue((s + 2) << 5, s & 1);
    }

    // ---- epilogue ----
    #pragma unroll
    for (int mt = 0; mt < 4; mt++) {
        #pragma unroll
        for (int nt = 0; nt < 2 * NT16; nt++) {
            int col0 = n0 + wn * 16 * NT16 + nt * 8 + 2 * tg;
            int r0 = m0 + wm * 64 + mt * 16 + g;
            #pragma unroll
            for (int ci = 0; ci < 4; ci++) {
                int r = r0 + (ci >> 1) * 8;
                int c = col0 + (ci & 1);
                if (r >= M || c >= N) continue;
                float v = alpha * acc[mt][nt][ci];
                if (bias) v += bias[c];
                if (EP == 1) {
                    float u = v;
                    v = 0.5f * u * (1.f + tanhf(0.7978845608028654f * (u + 0.044715f * u * u * u)));
                }
                if (EP == 2) v += res[(long long)r * ldc + c];
                if (rnd) v = rtf(v);
                C[(long long)r * ldc + c] = v;
            }
        }
    }
}

#define SMEM4 ((2*ABUF + 2*128*36) * 4)   // 73728
#define SMEM2 ((2*ABUF + 2*64*36) * 4)    // 55296

extern "C" void kernel_launch(void* const* d_in, const int* in_sizes, int n_in,
                              void* d_out, int out_size) {
    const int*   idx    = (const int*)  d_in[0];
    const float* wte    = (const float*)d_in[1];
    const float* wpe    = (const float*)d_in[2];
    const float* ln1_w  = (const float*)d_in[3];
    const float* ln1_b  = (const float*)d_in[4];
    const float* attn_w = (const float*)d_in[5];
    const float* attn_b = (const float*)d_in[6];
    const float* atp_w  = (const float*)d_in[7];
    const float* atp_b  = (const float*)d_in[8];
    const float* ln2_w  = (const float*)d_in[9];
    const float* ln2_b  = (const float*)d_in[10];
    const float* fc_w   = (const float*)d_in[11];
    const float* fc_b   = (const float*)d_in[12];
    const float* pr_w   = (const float*)d_in[13];
    const float* pr_b   = (const float*)d_in[14];
    const float* lnf_w  = (const float*)d_in[15];
    const float* lnf_b  = (const float*)d_in[16];
    float* out = (float*)d_out;

    float *gx, *gh, *gqkv, *gatt, *gy, *gm, *gvt;
    float *cw_attn, *cw_atp, *cw_fc, *cw_pr, *cw_wte;
    cudaGetSymbolAddress((void**)&gx,   g_x);
    cudaGetSymbolAddress((void**)&gh,   g_h);
    cudaGetSymbolAddress((void**)&gqkv, g_qkv);
    cudaGetSymbolAddress((void**)&gatt, g_att);
    cudaGetSymbolAddress((void**)&gy,   g_y);
    cudaGetSymbolAddress((void**)&gm,   g_m);
    cudaGetSymbolAddress((void**)&gvt,  g_vt);
    cudaGetSymbolAddress((void**)&cw_attn, c_attn_w);
    cudaGetSymbolAddress((void**)&cw_atp,  c_atp_w);
    cudaGetSymbolAddress((void**)&cw_fc,   c_fc_w);
    cudaGetSymbolAddress((void**)&cw_pr,   c_pr_w);
    cudaGetSymbolAddress((void**)&cw_wte,  c_wte);

    cudaFuncSetAttribute(gemm_tc<4,0>, cudaFuncAttributeMaxDynamicSharedMemorySize, SMEM4);
    cudaFuncSetAttribute(gemm_tc<4,1>, cudaFuncAttributeMaxDynamicSharedMemorySize, SMEM4);
    cudaFuncSetAttribute(gemm_tc<2,0>, cudaFuncAttributeMaxDynamicSharedMemorySize, SMEM2);
    cudaFuncSetAttribute(gemm_tc<2,2>, cudaFuncAttributeMaxDynamicSharedMemorySize, SMEM2);

    const float scale = 0.03608439182435161f;  // 1/sqrt(E)

    // ---- weight prepass: transpose + tf32 round ----
    {
        dim3 b(32, 8);
        transpose_round<<<dim3(3*EDIM/32, EDIM/32, NL), b>>>(attn_w, cw_attn, EDIM, 3*EDIM);
        transpose_round<<<dim3(EDIM/32,   EDIM/32, NL), b>>>(atp_w,  cw_atp,  EDIM, EDIM);
        transpose_round<<<dim3(4*EDIM/32, EDIM/32, NL), b>>>(fc_w,   cw_fc,   EDIM, 4*EDIM);
        transpose_round<<<dim3(EDIM/32, 4*EDIM/32, NL), b>>>(pr_w,   cw_pr,   4*EDIM, EDIM);
        tf32_round4<<<8192, 256>>>((const float4*)wte, (float4*)cw_wte, (int)((long long)VDIM*EDIM/4));
    }

    embed_kernel<<<BT, 256>>>(idx, wte, wpe);

    for (int l = 0; l < NL; l++) {
        layernorm_kernel<<<BT, 256>>>(gx, gh, ln1_w + l * EDIM, ln1_b + l * EDIM);

        // qkv = h @ attn_w + attn_b  (rounded out)
        {
            dim3 g(3 * EDIM / 128, BT / 128, 1);
            gemm_tc<4, 0><<<g, 128, SMEM4>>>(gh, 0, 0,
                                      cw_attn + (long long)l * EDIM * 3 * EDIM, 0, 0,
                                      gqkv, 0, 0,
                                      attn_b + l * 3 * EDIM, nullptr,
                                      BT, 3 * EDIM, EDIM, EDIM, EDIM, 3 * EDIM,
                                      1.f, 1, 1, 0);
        }
        // scores = scale * Q @ K^T  (causal tile skip; softmax rounds)
        {
            dim3 g(TDIM / 128, TDIM / 128, BDIM * NH);
            gemm_tc<4, 0><<<g, 128, SMEM4>>>(gqkv, (long long)TDIM * 3 * EDIM, HD,
                                      gqkv + EDIM, (long long)TDIM * 3 * EDIM, HD,
                                      gatt, (long long)NH * TDIM * TDIM, (long long)TDIM * TDIM,
                                      nullptr, nullptr,
                                      TDIM, TDIM, HD, 3 * EDIM, 3 * EDIM, TDIM,
                                      scale, NH, 0, 1);
        }
        {
            dim3 g(TDIM, BDIM * NH);
            softmax_kernel<<<g, 128>>>();
        }
        // V transpose -> g_vt
        v_transpose<<<dim3(TDIM / 32, HD / 32, BDIM * NH), dim3(32, 8)>>>();
        // y = attn @ V  (B = V^T n-major; rounded out)
        {
            dim3 g(1, TDIM / 128, BDIM * NH);
            gemm_tc<2, 0><<<g, 128, SMEM2>>>(gatt, (long long)NH * TDIM * TDIM, (long long)TDIM * TDIM,
                                      gvt, (long long)NH * HD * TDIM, (long long)HD * TDIM,
                                      gy, (long long)TDIM * EDIM, HD,
                                      nullptr, nullptr,
                                      TDIM, HD, TDIM, TDIM, TDIM, EDIM,
                                      1.f, NH, 1, 0);
        }
        // x = x + y @ atp_w + atp_b
        {
            dim3 g(EDIM / 64, BT / 128, 1);
            gemm_tc<2, 2><<<g, 128, SMEM2>>>(gy, 0, 0,
                                      cw_atp + (long long)l * EDIM * EDIM, 0, 0,
                                      gx, 0, 0,
                                      atp_b + l * EDIM, gx,
                                      BT, EDIM, EDIM, EDIM, EDIM, EDIM,
                                      1.f, 1, 0, 0);
        }
        layernorm_kernel<<<BT, 256>>>(gx, gh, ln2_w + l * EDIM, ln2_b + l * EDIM);

        // m = gelu(h @ fc_w + fc_b)  (rounded out)
        {
            dim3 g(4 * EDIM / 128, BT / 128, 1);
            gemm_tc<4, 1><<<g, 128, SMEM4>>>(gh, 0, 0,
                                      cw_fc + (long long)l * EDIM * 4 * EDIM, 0, 0,
                                      gm, 0, 0,
                                      fc_b + l * 4 * EDIM, nullptr,
                                      BT, 4 * EDIM, EDIM, EDIM, EDIM, 4 * EDIM,
                                      1.f, 1, 1, 0);
        }
        // x = x + m @ pr_w + pr_b
        {
            dim3 g(EDIM / 64, BT / 128, 1);
            gemm_tc<2, 2><<<g, 128, SMEM2>>>(gm, 0, 0,
                                      cw_pr + (long long)l * 4 * EDIM * EDIM, 0, 0,
                                      gx, 0, 0,
                                      pr_b + l * EDIM, gx,
                                      BT, EDIM, 4 * EDIM, 4 * EDIM, 4 * EDIM, EDIM,
                                      1.f, 1, 0, 0);
        }
    }

    layernorm_kernel<<<BT, 256>>>(gx, gh, lnf_w, lnf_b);

    // logits = h @ wte^T
    {
        dim3 g((VDIM + 127) / 128, BT / 128, 1);
        gemm_tc<4, 0><<<g, 128, SMEM4>>>(gh, 0, 0,
                                  cw_wte, 0, 0,
                                  out, 0, 0,
                                  nullptr, nullptr,
                                  BT, VDIM, EDIM, EDIM, EDIM, VDIM,
                                  1.f, 1, 0, 0);
    }
}

// round 7
// speedup vs baseline: 4.5554x; 1.3726x over previous
#include <cuda_runtime.h>
#include <cuda_fp16.h>
#include <math.h>
#include <stdint.h>

// Problem constants (GPT_5875515261622)
#define NL   4
#define NH   12
#define EDIM 768
#define TDIM 1024
#define BDIM 2
#define VDIM 50257
#define HD   64
#define BT   (BDIM*TDIM)

// ---- scratch (device globals; no runtime allocation allowed) ----
__device__ float  g_x  [BT*EDIM];
__device__ __half g_h  [BT*EDIM];
__device__ __half g_qkv[BT*3*EDIM];
__device__ float  g_att [(long long)BDIM*NH*TDIM*TDIM];  // scores (fp32)
__device__ __half g_attp[(long long)BDIM*NH*TDIM*TDIM];  // probs  (fp16)
__device__ __half g_y  [BT*EDIM];
__device__ __half g_m  [BT*4*EDIM];
__device__ __half g_vt [BDIM*NH*HD*TDIM];   // V^T per (b,h): [d][t]

// fp16 weight copies ([out][in] n-major where transposed)
__device__ __half c_attn_w[NL*EDIM*3*EDIM];
__device__ __half c_atp_w [NL*EDIM*EDIM];
__device__ __half c_fc_w  [NL*EDIM*4*EDIM];
__device__ __half c_pr_w  [NL*4*EDIM*EDIM];
__device__ __half c_wte   [(long long)VDIM*EDIM];

// ---- fp16 conversion prepass (float4 -> 4 halves) ----
__global__ void half_convert4(const float4* __restrict__ in, __half2* __restrict__ out, int n4) {
    for (int i = blockIdx.x * blockDim.x + threadIdx.x; i < n4; i += gridDim.x * blockDim.x) {
        float4 v = in[i];
        out[2*i]   = __floats2half2_rn(v.x, v.y);
        out[2*i+1] = __floats2half2_rn(v.z, v.w);
    }
}

// ---- transpose + fp16: in [K][N] float row-major -> out [N][K] half ----
__global__ void transpose_half(const float* __restrict__ in, __half* __restrict__ out,
                               int K, int N) {
    __shared__ float t[32][33];
    long long zoff = (long long)blockIdx.z * K * N;
    in += zoff; out += zoff;
    int n0 = blockIdx.x * 32, k0 = blockIdx.y * 32;
    int x = threadIdx.x, y = threadIdx.y;
    #pragma unroll
    for (int i = y; i < 32; i += 8)
        t[i][x] = in[(long long)(k0 + i) * N + n0 + x];
    __syncthreads();
    #pragma unroll
    for (int i = y; i < 32; i += 8)
        out[(long long)(n0 + i) * K + k0 + x] = __float2half_rn(t[x][i]);
}

// ---- V transpose: g_qkv V-slice [t][d] half -> g_vt[(b*NH+h)][d][t] ----
__global__ void v_transpose() {
    __shared__ __half t[32][33];
    int z = blockIdx.z;
    int b = z / NH, h = z % NH;
    int t0 = blockIdx.x * 32, d0 = blockIdx.y * 32;
    int x = threadIdx.x, y = threadIdx.y;
    #pragma unroll
    for (int i = y; i < 32; i += 8)
        t[i][x] = g_qkv[((long long)(b * TDIM + t0 + i)) * (3 * EDIM) + 2 * EDIM + h * HD + d0 + x];
    __syncthreads();
    #pragma unroll
    for (int i = y; i < 32; i += 8)
        g_vt[((long long)z * HD + d0 + i) * TDIM + t0 + x] = t[x][i];
}

// ---- embedding ----
__global__ void embed_kernel(const int* __restrict__ idx,
                             const float* __restrict__ wte,
                             const float* __restrict__ wpe) {
    int row = blockIdx.x;
    int t   = row % TDIM;
    long long tok = idx[row];
    const float* src = wte + tok * EDIM;
    const float* pos = wpe + (long long)t * EDIM;
    float* dst = g_x + (long long)row * EDIM;
    for (int c = threadIdx.x; c < EDIM; c += blockDim.x)
        dst[c] = src[c] + pos[c];
}

// ---- layernorm (fp32 in, fp16 out) ----
__global__ void layernorm_kernel(const float* __restrict__ in,
                                 __half* __restrict__ out,
                                 const float* __restrict__ w,
                                 const float* __restrict__ b) {
    int row = blockIdx.x;
    const float* x = in + (long long)row * EDIM;
    __half* o = out + (long long)row * EDIM;
    __shared__ float red[256];
    float s = 0.f;
    for (int c = threadIdx.x; c < EDIM; c += blockDim.x) s += x[c];
    red[threadIdx.x] = s; __syncthreads();
    for (int st = 128; st > 0; st >>= 1) {
        if (threadIdx.x < st) red[threadIdx.x] += red[threadIdx.x + st];
        __syncthreads();
    }
    float mu = red[0] * (1.f / EDIM);
    __syncthreads();
    float v = 0.f;
    for (int c = threadIdx.x; c < EDIM; c += blockDim.x) { float d = x[c] - mu; v += d * d; }
    red[threadIdx.x] = v; __syncthreads();
    for (int st = 128; st > 0; st >>= 1) {
        if (threadIdx.x < st) red[threadIdx.x] += red[threadIdx.x + st];
        __syncthreads();
    }
    float rstd = rsqrtf(red[0] * (1.f / EDIM) + 1e-5f);
    for (int c = threadIdx.x; c < EDIM; c += blockDim.x)
        o[c] = __float2half_rn((x[c] - mu) * rstd * w[c] + b[c]);
}

// ---- causal softmax: fp32 scores in, fp16 probs out (zeros masked tail) ----
__global__ void softmax_kernel() {
    int i = blockIdx.x;
    long long z = blockIdx.y;
    const float* row = g_att + (z * TDIM + i) * (long long)TDIM;
    __half* orow = g_attp + (z * TDIM + i) * (long long)TDIM;
    int n = i + 1;
    __shared__ float red[128];
    __shared__ float ex[TDIM];
    float mx = -1e30f;
    for (int j = threadIdx.x; j < n; j += blockDim.x) mx = fmaxf(mx, row[j]);
    red[threadIdx.x] = mx; __syncthreads();
    for (int st = 64; st > 0; st >>= 1) {
        if (threadIdx.x < st) red[threadIdx.x] = fmaxf(red[threadIdx.x], red[threadIdx.x + st]);
        __syncthreads();
    }
    mx = red[0]; __syncthreads();
    float s = 0.f;
    for (int j = threadIdx.x; j < n; j += blockDim.x) { float e = __expf(row[j] - mx); ex[j] = e; s += e; }
    red[threadIdx.x] = s; __syncthreads();
    for (int st = 64; st > 0; st >>= 1) {
        if (threadIdx.x < st) red[threadIdx.x] += red[threadIdx.x + st];
        __syncthreads();
    }
    float inv = 1.f / red[0];
    for (int j = threadIdx.x; j < n; j += blockDim.x) orow[j] = __float2half_rn(ex[j] * inv);
    const __half hz = __float2half_rn(0.f);
    for (int j = n + threadIdx.x; j < TDIM; j += blockDim.x) orow[j] = hz;
}

// ======================= fp16 mma.sync GEMM =======================
// C[M,N] = alpha*(A[M,K] @ B[N,K]^T) + bias [+gelu | +residual]
// A,B: fp16, k-major rows. CTA 128m x (32*NT16)n, 4 warps (2x2) of 64 x (16*NT16).
// smem stride 40 halves; ldmatrix.x4.b16 fragments; mma.m16n8k16; cp.async 2-stage.
// EP: 0 none, 1 gelu, 2 +residual. OT: 0 float out, 1 half out.
#define LDH 40

template<int NT16, int EP, int OT>
__global__ void __launch_bounds__(128, NT16 == 4 ? 2 : 3)
gemm_fp16(const __half* __restrict__ A, long long sAb, long long sAh,
          const __half* __restrict__ Bm, long long sBb, long long sBh,
          void* __restrict__ Cv, long long sCb, long long sCh,
          const float* __restrict__ bias,
          const float* __restrict__ res,
          int M, int N, int K, int lda, int ldb, int ldc,
          float alpha, int zdiv, int causal)
{
    extern __shared__ char smc[];
    const int BROWS = 32 * NT16;
    const int ASTG = 128 * LDH;          // halves per A stage
    const int BSTG = BROWS * LDH;
    __half* base = (__half*)smc;
    __half* AsB[2] = { base, base + ASTG };
    __half* BsB[2] = { base + 2 * ASTG, base + 2 * ASTG + BSTG };

    const int m0 = blockIdx.x * 128;
    const int n0 = blockIdx.y * BROWS;
    if (causal && n0 >= m0 + 128) return;

    int z = blockIdx.z;
    int zb = z / zdiv, zh = z % zdiv;
    A  += zb * sAb + zh * sAh;
    Bm += zb * sBb + zh * sBh;
    float* Cf = (float*)Cv + zb * sCb + zh * sCh;
    __half* Ch = (__half*)Cv + zb * sCb + zh * sCh;
    if (EP == 2) res += zb * sCb + zh * sCh;

    const int tid = threadIdx.x;
    const int warp = tid >> 5, lane = tid & 31;
    const int g = lane >> 2, tg = lane & 3;
    const int wm = warp >> 1, wn = warp & 1;
    const int quad = lane >> 3, rsel = lane & 7;

    float acc[4][2 * NT16][4];
    #pragma unroll
    for (int mt = 0; mt < 4; mt++)
        #pragma unroll
        for (int nt = 0; nt < 2 * NT16; nt++)
            #pragma unroll
            for (int c = 0; c < 4; c++) acc[mt][nt][c] = 0.f;

    // ldmatrix per-lane byte offsets (within a stage), k-step 0
    unsigned aoff[4], boff[NT16];
    #pragma unroll
    for (int mt = 0; mt < 4; mt++)
        aoff[mt] = (unsigned)(((wm * 64 + mt * 16 + (quad & 1) * 8 + rsel) * LDH
                               + (quad >> 1) * 8) * 2);
    #pragma unroll
    for (int p = 0; p < NT16; p++)
        boff[p] = (unsigned)(((wn * 16 * NT16 + p * 16 + (quad & 1) * 8 + rsel) * LDH
                              + (quad >> 1) * 8) * 2);

    unsigned sA[2] = { (unsigned)__cvta_generic_to_shared(AsB[0]),
                       (unsigned)__cvta_generic_to_shared(AsB[1]) };
    unsigned sB[2] = { (unsigned)__cvta_generic_to_shared(BsB[0]),
                       (unsigned)__cvta_generic_to_shared(BsB[1]) };

    // one 32-half k-slab
    auto issue = [&](int k0, int buf) {
        unsigned ab = sA[buf], bb = sB[buf];
        #pragma unroll
        for (int it = 0; it < 4; it++) {
            int idx = tid + it * 128;
            int row = idx >> 2, seg = idx & 3;
            const __half* src = &A[(long long)(m0 + row) * lda + k0 + seg * 8];
            unsigned dst = ab + (unsigned)(row * LDH + seg * 8) * 2u;
            asm volatile("cp.async.cg.shared.global [%0], [%1], 16;\n"
                         :: "r"(dst), "l"(src));
        }
        #pragma unroll
        for (int it = 0; it < NT16; it++) {
            int idx = tid + it * 128;
            int nn = idx >> 2, seg = idx & 3;
            int gn = n0 + nn;
            const __half* src = &Bm[(long long)gn * ldb + k0 + seg * 8];
            int sz = (gn < N) ? 16 : 0;
            if (!sz) src = Bm;
            unsigned dst = bb + (unsigned)(nn * LDH + seg * 8) * 2u;
            asm volatile("cp.async.cg.shared.global [%0], [%1], 16, %2;\n"
                         :: "r"(dst), "l"(src), "r"(sz));
        }
        asm volatile("cp.async.commit_group;\n" ::: "memory");
    };

    const int S = K >> 5;
    issue(0, 0);
    if (S > 1) issue(32, 1);

    for (int s = 0; s < S; s++) {
        if (s + 1 < S) asm volatile("cp.async.wait_group 1;\n" ::: "memory");
        else           asm volatile("cp.async.wait_group 0;\n" ::: "memory");
        __syncthreads();
        unsigned abase = sA[s & 1], bbase = sB[s & 1];
        #pragma unroll
        for (int kk = 0; kk < 2; kk++) {
            unsigned af[4][4];
            #pragma unroll
            for (int mt = 0; mt < 4; mt++) {
                asm volatile("ldmatrix.sync.aligned.m8n8.x4.shared.b16 {%0,%1,%2,%3}, [%4];"
                             : "=r"(af[mt][0]), "=r"(af[mt][1]), "=r"(af[mt][2]), "=r"(af[mt][3])
                             : "r"(abase + aoff[mt] + (unsigned)(kk * 32)));
            }
            unsigned bf[2 * NT16][2];
            #pragma unroll
            for (int p = 0; p < NT16; p++) {
                unsigned r0, r1, r2, r3;
                asm volatile("ldmatrix.sync.aligned.m8n8.x4.shared.b16 {%0,%1,%2,%3}, [%4];"
                             : "=r"(r0), "=r"(r1), "=r"(r2), "=r"(r3)
                             : "r"(bbase + boff[p] + (unsigned)(kk * 32)));
                bf[2 * p][0] = r0;     bf[2 * p][1] = r2;
                bf[2 * p + 1][0] = r1; bf[2 * p + 1][1] = r3;
            }
            #pragma unroll
            for (int mt = 0; mt < 4; mt++)
                #pragma unroll
                for (int nt = 0; nt < 2 * NT16; nt++) {
                    asm volatile(
                        "mma.sync.aligned.m16n8k16.row.col.f32.f16.f16.f32 "
                        "{%0,%1,%2,%3}, {%4,%5,%6,%7}, {%8,%9}, {%0,%1,%2,%3};\n"
                        : "+f"(acc[mt][nt][0]), "+f"(acc[mt][nt][1]),
                          "+f"(acc[mt][nt][2]), "+f"(acc[mt][nt][3])
                        : "r"(af[mt][0]), "r"(af[mt][1]), "r"(af[mt][2]), "r"(af[mt][3]),
                          "r"(bf[nt][0]), "r"(bf[nt][1]));
                }
        }
        __syncthreads();
        if (s + 2 < S) issue((s + 2) << 5, s & 1);
    }

    // ---- epilogue ----
    #pragma unroll
    for (int mt = 0; mt < 4; mt++) {
        #pragma unroll
        for (int nt = 0; nt < 2 * NT16; nt++) {
            int col0 = n0 + wn * 16 * NT16 + nt * 8 + 2 * tg;
            int r0 = m0 + wm * 64 + mt * 16 + g;
            #pragma unroll
            for (int ci = 0; ci < 4; ci++) {
                int r = r0 + (ci >> 1) * 8;
                int c = col0 + (ci & 1);
                if (c >= N) continue;
                float v = alpha * acc[mt][nt][ci];
                if (bias) v += bias[c];
                if (EP == 1) {
                    float u = v;
                    v = 0.5f * u * (1.f + tanhf(0.7978845608028654f * (u + 0.044715f * u * u * u)));
                }
                if (EP == 2) v += res[(long long)r * ldc + c];
                if (OT == 0) Cf[(long long)r * ldc + c] = v;
                else         Ch[(long long)r * ldc + c] = __float2half_rn(v);
            }
        }
    }
}

#define SMEM_H4 (2 * (128*LDH + 128*LDH) * 2)   // 40960
#define SMEM_H2 (2 * (128*LDH + 64*LDH) * 2)    // 30720

extern "C" void kernel_launch(void* const* d_in, const int* in_sizes, int n_in,
                              void* d_out, int out_size) {
    const int*   idx    = (const int*)  d_in[0];
    const float* wte    = (const float*)d_in[1];
    const float* wpe    = (const float*)d_in[2];
    const float* ln1_w  = (const float*)d_in[3];
    const float* ln1_b  = (const float*)d_in[4];
    const float* attn_w = (const float*)d_in[5];
    const float* attn_b = (const float*)d_in[6];
    const float* atp_w  = (const float*)d_in[7];
    const float* atp_b  = (const float*)d_in[8];
    const float* ln2_w  = (const float*)d_in[9];
    const float* ln2_b  = (const float*)d_in[10];
    const float* fc_w   = (const float*)d_in[11];
    const float* fc_b   = (const float*)d_in[12];
    const float* pr_w   = (const float*)d_in[13];
    const float* pr_b   = (const float*)d_in[14];
    const float* lnf_w  = (const float*)d_in[15];
    const float* lnf_b  = (const float*)d_in[16];
    float* out = (float*)d_out;

    float *gx; __half *gh, *gqkv, *gy, *gm, *gvt, *gattp;
    float *gatt;
    __half *cw_attn, *cw_atp, *cw_fc, *cw_pr, *cw_wte;
    cudaGetSymbolAddress((void**)&gx,    g_x);
    cudaGetSymbolAddress((void**)&gh,    g_h);
    cudaGetSymbolAddress((void**)&gqkv,  g_qkv);
    cudaGetSymbolAddress((void**)&gatt,  g_att);
    cudaGetSymbolAddress((void**)&gattp, g_attp);
    cudaGetSymbolAddress((void**)&gy,    g_y);
    cudaGetSymbolAddress((void**)&gm,    g_m);
    cudaGetSymbolAddress((void**)&gvt,   g_vt);
    cudaGetSymbolAddress((void**)&cw_attn, c_attn_w);
    cudaGetSymbolAddress((void**)&cw_atp,  c_atp_w);
    cudaGetSymbolAddress((void**)&cw_fc,   c_fc_w);
    cudaGetSymbolAddress((void**)&cw_pr,   c_pr_w);
    cudaGetSymbolAddress((void**)&cw_wte,  c_wte);

    cudaFuncSetAttribute(gemm_fp16<4,0,0>, cudaFuncAttributeMaxDynamicSharedMemorySize, SMEM_H4);
    cudaFuncSetAttribute(gemm_fp16<4,0,1>, cudaFuncAttributeMaxDynamicSharedMemorySize, SMEM_H4);
    cudaFuncSetAttribute(gemm_fp16<4,1,1>, cudaFuncAttributeMaxDynamicSharedMemorySize, SMEM_H4);
    cudaFuncSetAttribute(gemm_fp16<2,2,0>, cudaFuncAttributeMaxDynamicSharedMemorySize, SMEM_H2);
    cudaFuncSetAttribute(gemm_fp16<2,0,1>, cudaFuncAttributeMaxDynamicSharedMemorySize, SMEM_H2);

    const float scale = 0.03608439182435161f;  // 1/sqrt(E)

    // ---- weight prepass: transpose (+fp16) / convert ----
    {
        dim3 b(32, 8);
        transpose_half<<<dim3(3*EDIM/32, EDIM/32, NL), b>>>(attn_w, cw_attn, EDIM, 3*EDIM);
        transpose_half<<<dim3(EDIM/32,   EDIM/32, NL), b>>>(atp_w,  cw_atp,  EDIM, EDIM);
        transpose_half<<<dim3(4*EDIM/32, EDIM/32, NL), b>>>(fc_w,   cw_fc,   EDIM, 4*EDIM);
        transpose_half<<<dim3(EDIM/32, 4*EDIM/32, NL), b>>>(pr_w,   cw_pr,   4*EDIM, EDIM);
        half_convert4<<<8192, 256>>>((const float4*)wte, (__half2*)cw_wte,
                                     (int)((long long)VDIM*EDIM/4));
    }

    embed_kernel<<<BT, 256>>>(idx, wte, wpe);

    for (int l = 0; l < NL; l++) {
        layernorm_kernel<<<BT, 256>>>(gx, gh, ln1_w + l * EDIM, ln1_b + l * EDIM);

        // qkv = h @ attn_w + attn_b  -> half
        {
            dim3 g(BT / 128, 3 * EDIM / 128, 1);
            gemm_fp16<4, 0, 1><<<g, 128, SMEM_H4>>>(gh, 0, 0,
                                      cw_attn + (long long)l * EDIM * 3 * EDIM, 0, 0,
                                      gqkv, 0, 0,
                                      attn_b + l * 3 * EDIM, nullptr,
                                      BT, 3 * EDIM, EDIM, EDIM, EDIM, 3 * EDIM,
                                      1.f, 1, 0);
        }
        // scores = scale * Q @ K^T -> float (causal tile skip)
        {
            dim3 g(TDIM / 128, TDIM / 128, BDIM * NH);
            gemm_fp16<4, 0, 0><<<g, 128, SMEM_H4>>>(gqkv, (long long)TDIM * 3 * EDIM, HD,
                                      gqkv + EDIM, (long long)TDIM * 3 * EDIM, HD,
                                      gatt, (long long)NH * TDIM * TDIM, (long long)TDIM * TDIM,
                                      nullptr, nullptr,
                                      TDIM, TDIM, HD, 3 * EDIM, 3 * EDIM, TDIM,
                                      scale, NH, 1);
        }
        {
            dim3 g(TDIM, BDIM * NH);
            softmax_kernel<<<g, 128>>>();
        }
        v_transpose<<<dim3(TDIM / 32, HD / 32, BDIM * NH), dim3(32, 8)>>>();
        // y = attn @ V -> half
        {
            dim3 g(TDIM / 128, 1, BDIM * NH);
            gemm_fp16<2, 0, 1><<<g, 128, SMEM_H2>>>(gattp, (long long)NH * TDIM * TDIM, (long long)TDIM * TDIM,
                                      gvt, (long long)NH * HD * TDIM, (long long)HD * TDIM,
                                      gy, (long long)TDIM * EDIM, HD,
                                      nullptr, nullptr,
                                      TDIM, HD, TDIM, TDIM, TDIM, EDIM,
                                      1.f, NH, 0);
        }
        // x = x + y @ atp_w + atp_b  -> float
        {
            dim3 g(BT / 128, EDIM / 64, 1);
            gemm_fp16<2, 2, 0><<<g, 128, SMEM_H2>>>(gy, 0, 0,
                                      cw_atp + (long long)l * EDIM * EDIM, 0, 0,
                                      gx, 0, 0,
                                      atp_b + l * EDIM, gx,
                                      BT, EDIM, EDIM, EDIM, EDIM, EDIM,
                                      1.f, 1, 0);
        }
        layernorm_kernel<<<BT, 256>>>(gx, gh, ln2_w + l * EDIM, ln2_b + l * EDIM);

        // m = gelu(h @ fc_w + fc_b) -> half
        {
            dim3 g(BT / 128, 4 * EDIM / 128, 1);
            gemm_fp16<4, 1, 1><<<g, 128, SMEM_H4>>>(gh, 0, 0,
                                      cw_fc + (long long)l * EDIM * 4 * EDIM, 0, 0,
                                      gm, 0, 0,
                                      fc_b + l * 4 * EDIM, nullptr,
                                      BT, 4 * EDIM, EDIM, EDIM, EDIM, 4 * EDIM,
                                      1.f, 1, 0);
        }
        // x = x + m @ pr_w + pr_b  -> float
        {
            dim3 g(BT / 128, EDIM / 64, 1);
            gemm_fp16<2, 2, 0><<<g, 128, SMEM_H2>>>(gm, 0, 0,
                                      cw_pr + (long long)l * 4 * EDIM * EDIM, 0, 0,
                                      gx, 0, 0,
                                      pr_b + l * EDIM, gx,
                                      BT, EDIM, 4 * EDIM, 4 * EDIM, 4 * EDIM, EDIM,
                                      1.f, 1, 0);
        }
    }

    layernorm_kernel<<<BT, 256>>>(gx, gh, lnf_w, lnf_b);

    // logits = h @ wte^T -> float  (m fastest for wte L2 reuse)
    {
        dim3 g(BT / 128, (VDIM + 127) / 128, 1);
        gemm_fp16<4, 0, 0><<<g, 128, SMEM_H4>>>(gh, 0, 0,
                                  cw_wte, 0, 0,
                                  out, 0, 0,
                                  nullptr, nullptr,
                                  BT, VDIM, EDIM, EDIM, EDIM, VDIM,
                                  1.f, 1, 0);
    }
}

// round 8
// speedup vs baseline: 5.1101x; 1.1218x over previous
#include <cuda_runtime.h>
#include <cuda_fp16.h>
#include <math.h>
#include <stdint.h>

// Problem constants (GPT_5875515261622)
#define NL   4
#define NH   12
#define EDIM 768
#define TDIM 1024
#define BDIM 2
#define VDIM 50257
#define HD   64
#define BT   (BDIM*TDIM)

// ---- scratch (device globals; no runtime allocation allowed) ----
__device__ float  g_x  [BT*EDIM];
__device__ __half g_h  [BT*EDIM];
__device__ __half g_qkv[BT*3*EDIM];
__device__ __half g_y  [BT*EDIM];
__device__ __half g_m  [BT*4*EDIM];
__device__ __half g_vt [BDIM*NH*HD*TDIM];   // V^T per (b,h): [d][t]

// fp16 weight copies ([out][in] n-major where transposed)
__device__ __half c_attn_w[NL*EDIM*3*EDIM];
__device__ __half c_atp_w [NL*EDIM*EDIM];
__device__ __half c_fc_w  [NL*EDIM*4*EDIM];
__device__ __half c_pr_w  [NL*4*EDIM*EDIM];
__device__ __half c_wte   [(long long)VDIM*EDIM];

// ---- fp16 conversion prepass ----
__global__ void half_convert4(const float4* __restrict__ in, __half2* __restrict__ out, int n4) {
    for (int i = blockIdx.x * blockDim.x + threadIdx.x; i < n4; i += gridDim.x * blockDim.x) {
        float4 v = in[i];
        out[2*i]   = __floats2half2_rn(v.x, v.y);
        out[2*i+1] = __floats2half2_rn(v.z, v.w);
    }
}

// ---- transpose + fp16: in [K][N] float row-major -> out [N][K] half ----
__global__ void transpose_half(const float* __restrict__ in, __half* __restrict__ out,
                               int K, int N) {
    __shared__ float t[32][33];
    long long zoff = (long long)blockIdx.z * K * N;
    in += zoff; out += zoff;
    int n0 = blockIdx.x * 32, k0 = blockIdx.y * 32;
    int x = threadIdx.x, y = threadIdx.y;
    #pragma unroll
    for (int i = y; i < 32; i += 8)
        t[i][x] = in[(long long)(k0 + i) * N + n0 + x];
    __syncthreads();
    #pragma unroll
    for (int i = y; i < 32; i += 8)
        out[(long long)(n0 + i) * K + k0 + x] = __float2half_rn(t[x][i]);
}

// ---- V transpose: g_qkv V-slice [t][d] half -> g_vt[(b*NH+h)][d][t] ----
__global__ void v_transpose() {
    __shared__ __half t[32][33];
    int z = blockIdx.z;
    int b = z / NH, h = z % NH;
    int t0 = blockIdx.x * 32, d0 = blockIdx.y * 32;
    int x = threadIdx.x, y = threadIdx.y;
    #pragma unroll
    for (int i = y; i < 32; i += 8)
        t[i][x] = g_qkv[((long long)(b * TDIM + t0 + i)) * (3 * EDIM) + 2 * EDIM + h * HD + d0 + x];
    __syncthreads();
    #pragma unroll
    for (int i = y; i < 32; i += 8)
        g_vt[((long long)z * HD + d0 + i) * TDIM + t0 + x] = t[x][i];
}

// ---- embedding ----
__global__ void embed_kernel(const int* __restrict__ idx,
                             const float* __restrict__ wte,
                             const float* __restrict__ wpe) {
    int row = blockIdx.x;
    int t   = row % TDIM;
    long long tok = idx[row];
    const float* src = wte + tok * EDIM;
    const float* pos = wpe + (long long)t * EDIM;
    float* dst = g_x + (long long)row * EDIM;
    for (int c = threadIdx.x; c < EDIM; c += blockDim.x)
        dst[c] = src[c] + pos[c];
}

// ---- layernorm (fp32 in, fp16 out) ----
__global__ void layernorm_kernel(const float* __restrict__ in,
                                 __half* __restrict__ out,
                                 const float* __restrict__ w,
                                 const float* __restrict__ b) {
    int row = blockIdx.x;
    const float* x = in + (long long)row * EDIM;
    __half* o = out + (long long)row * EDIM;
    __shared__ float red[256];
    float s = 0.f;
    for (int c = threadIdx.x; c < EDIM; c += blockDim.x) s += x[c];
    red[threadIdx.x] = s; __syncthreads();
    for (int st = 128; st > 0; st >>= 1) {
        if (threadIdx.x < st) red[threadIdx.x] += red[threadIdx.x + st];
        __syncthreads();
    }
    float mu = red[0] * (1.f / EDIM);
    __syncthreads();
    float v = 0.f;
    for (int c = threadIdx.x; c < EDIM; c += blockDim.x) { float d = x[c] - mu; v += d * d; }
    red[threadIdx.x] = v; __syncthreads();
    for (int st = 128; st > 0; st >>= 1) {
        if (threadIdx.x < st) red[threadIdx.x] += red[threadIdx.x + st];
        __syncthreads();
    }
    float rstd = rsqrtf(red[0] * (1.f / EDIM) + 1e-5f);
    for (int c = threadIdx.x; c < EDIM; c += blockDim.x)
        o[c] = __float2half_rn((x[c] - mu) * rstd * w[c] + b[c]);
}

// ======================= fused flash attention =======================
// Per CTA: 128 q-rows of one (b,h). 4 warps x 32 q-rows. K/V tiles of 64,
// cp.async double-buffered, online softmax fp32, PV in fp16 mma.
#define FLDH 72

__global__ void __launch_bounds__(128, 1)
flash_attn(float scale)
{
    extern __shared__ __half fsm[];
    __half* Qs = fsm;                                  // 128 x FLDH
    const int qb = gridDim.x - 1 - blockIdx.x;         // heavy blocks first
    const int q0 = qb * 128;
    const int z = blockIdx.y;
    const int b = z / NH, h = z % NH;

    const __half* Qg = g_qkv + (long long)b * TDIM * (3 * EDIM) + h * HD;
    const __half* Kg = Qg + EDIM;
    const __half* Vg = g_vt + (long long)z * HD * TDIM;

    const int tid = threadIdx.x;
    const int warp = tid >> 5, lane = tid & 31;
    const int g = lane >> 2, tg = lane & 3;
    const int quad = lane >> 3, rsel = lane & 7;

    unsigned sQ = (unsigned)__cvta_generic_to_shared(Qs);
    unsigned sK[2] = { sQ + 128u * FLDH * 2u, sQ + (128u + 64u) * FLDH * 2u };
    unsigned sV[2] = { sQ + (128u + 128u) * FLDH * 2u, sQ + (128u + 192u) * FLDH * 2u };

    // load Q tile (128 x 64)
    #pragma unroll
    for (int it = 0; it < 8; it++) {
        int idx = tid + it * 128;
        int row = idx >> 3, seg = idx & 7;
        const __half* src = &Qg[(long long)(q0 + row) * (3 * EDIM) + seg * 8];
        unsigned dst = sQ + (unsigned)(row * FLDH + seg * 8) * 2u;
        asm volatile("cp.async.cg.shared.global [%0], [%1], 16;\n" :: "r"(dst), "l"(src));
    }
    auto issueKV = [&](int k0, int buf) {
        #pragma unroll
        for (int it = 0; it < 4; it++) {
            int idx = tid + it * 128;
            int row = idx >> 3, seg = idx & 7;
            const __half* src = &Kg[(long long)(k0 + row) * (3 * EDIM) + seg * 8];
            unsigned dst = sK[buf] + (unsigned)(row * FLDH + seg * 8) * 2u;
            asm volatile("cp.async.cg.shared.global [%0], [%1], 16;\n" :: "r"(dst), "l"(src));
        }
        #pragma unroll
        for (int it = 0; it < 4; it++) {
            int idx = tid + it * 128;
            int d = idx >> 3, seg = idx & 7;
            const __half* src = &Vg[(long long)d * TDIM + k0 + seg * 8];
            unsigned dst = sV[buf] + (unsigned)(d * FLDH + seg * 8) * 2u;
            asm volatile("cp.async.cg.shared.global [%0], [%1], 16;\n" :: "r"(dst), "l"(src));
        }
        asm volatile("cp.async.commit_group;\n" ::: "memory");
    };

    const int St = 2 * qb + 2;   // tiles: k0 = 0..q0+64 step 64
    issueKV(0, 0);               // group 0 = Q + KV0
    issueKV(64, 1);              // St >= 2 always

    // ldmatrix per-lane offsets
    unsigned aoffQ[2], boffB[4];
    #pragma unroll
    for (int mt = 0; mt < 2; mt++)
        aoffQ[mt] = (unsigned)(((warp * 32 + mt * 16 + (quad & 1) * 8 + rsel) * FLDH
                                + (quad >> 1) * 8) * 2);
    #pragma unroll
    for (int p = 0; p < 4; p++)
        boffB[p] = (unsigned)(((p * 16 + (quad & 1) * 8 + rsel) * FLDH
                               + (quad >> 1) * 8) * 2);

    float m_s[2][2], l_s[2][2];
    float oacc[2][8][4];
    #pragma unroll
    for (int mt = 0; mt < 2; mt++)
        #pragma unroll
        for (int hp = 0; hp < 2; hp++) { m_s[mt][hp] = -1e30f; l_s[mt][hp] = 0.f; }
    #pragma unroll
    for (int mt = 0; mt < 2; mt++)
        #pragma unroll
        for (int nt = 0; nt < 8; nt++)
            #pragma unroll
            for (int c = 0; c < 4; c++) oacc[mt][nt][c] = 0.f;

    for (int s = 0; s < St; s++) {
        if (s + 1 < St) asm volatile("cp.async.wait_group 1;\n" ::: "memory");
        else            asm volatile("cp.async.wait_group 0;\n" ::: "memory");
        __syncthreads();
        const int k0 = s * 64;
        unsigned kb = sK[s & 1], vb = sV[s & 1];

        // ---- S = scale * Q @ K^T ----
        float sacc[2][8][4];
        #pragma unroll
        for (int mt = 0; mt < 2; mt++)
            #pragma unroll
            for (int nt = 0; nt < 8; nt++)
                #pragma unroll
                for (int c = 0; c < 4; c++) sacc[mt][nt][c] = 0.f;
        #pragma unroll
        for (int kk = 0; kk < 4; kk++) {
            unsigned af[2][4];
            #pragma unroll
            for (int mt = 0; mt < 2; mt++)
                asm volatile("ldmatrix.sync.aligned.m8n8.x4.shared.b16 {%0,%1,%2,%3}, [%4];"
                             : "=r"(af[mt][0]), "=r"(af[mt][1]), "=r"(af[mt][2]), "=r"(af[mt][3])
                             : "r"(sQ + aoffQ[mt] + (unsigned)(kk * 32)));
            unsigned bf[8][2];
            #pragma unroll
            for (int p = 0; p < 4; p++) {
                unsigned r0, r1, r2, r3;
                asm volatile("ldmatrix.sync.aligned.m8n8.x4.shared.b16 {%0,%1,%2,%3}, [%4];"
                             : "=r"(r0), "=r"(r1), "=r"(r2), "=r"(r3)
                             : "r"(kb + boffB[p] + (unsigned)(kk * 32)));
                bf[2*p][0] = r0;   bf[2*p][1] = r2;
                bf[2*p+1][0] = r1; bf[2*p+1][1] = r3;
            }
            #pragma unroll
            for (int mt = 0; mt < 2; mt++)
                #pragma unroll
                for (int nt = 0; nt < 8; nt++)
                    asm volatile(
                        "mma.sync.aligned.m16n8k16.row.col.f32.f16.f16.f32 "
                        "{%0,%1,%2,%3}, {%4,%5,%6,%7}, {%8,%9}, {%0,%1,%2,%3};\n"
                        : "+f"(sacc[mt][nt][0]), "+f"(sacc[mt][nt][1]),
                          "+f"(sacc[mt][nt][2]), "+f"(sacc[mt][nt][3])
                        : "r"(af[mt][0]), "r"(af[mt][1]), "r"(af[mt][2]), "r"(af[mt][3]),
                          "r"(bf[nt][0]), "r"(bf[nt][1]));
        }

        // ---- scale + causal mask ----
        const int rwb = q0 + warp * 32;
        if (k0 + 63 > rwb) {
            #pragma unroll
            for (int mt = 0; mt < 2; mt++)
                #pragma unroll
                for (int nt = 0; nt < 8; nt++)
                    #pragma unroll
                    for (int c = 0; c < 4; c++) {
                        int r = rwb + mt * 16 + g + ((c >> 1) << 3);
                        int j = k0 + nt * 8 + 2 * tg + (c & 1);
                        sacc[mt][nt][c] = (j > r) ? -1e30f : sacc[mt][nt][c] * scale;
                    }
        } else {
            #pragma unroll
            for (int mt = 0; mt < 2; mt++)
                #pragma unroll
                for (int nt = 0; nt < 8; nt++)
                    #pragma unroll
                    for (int c = 0; c < 4; c++) sacc[mt][nt][c] *= scale;
        }

        // ---- online softmax update ----
        #pragma unroll
        for (int mt = 0; mt < 2; mt++) {
            #pragma unroll
            for (int hp = 0; hp < 2; hp++) {
                float rmax = -1e30f;
                #pragma unroll
                for (int nt = 0; nt < 8; nt++)
                    rmax = fmaxf(rmax, fmaxf(sacc[mt][nt][2*hp], sacc[mt][nt][2*hp+1]));
                rmax = fmaxf(rmax, __shfl_xor_sync(0xffffffffu, rmax, 1));
                rmax = fmaxf(rmax, __shfl_xor_sync(0xffffffffu, rmax, 2));
                float mold = m_s[mt][hp];
                float mnew = fmaxf(mold, rmax);
                float corr = __expf(mold - mnew);
                float rsum = 0.f;
                #pragma unroll
                for (int nt = 0; nt < 8; nt++) {
                    float p0 = __expf(sacc[mt][nt][2*hp]   - mnew);
                    float p1 = __expf(sacc[mt][nt][2*hp+1] - mnew);
                    sacc[mt][nt][2*hp] = p0; sacc[mt][nt][2*hp+1] = p1;
                    rsum += p0 + p1;
                }
                rsum += __shfl_xor_sync(0xffffffffu, rsum, 1);
                rsum += __shfl_xor_sync(0xffffffffu, rsum, 2);
                l_s[mt][hp] = l_s[mt][hp] * corr + rsum;
                m_s[mt][hp] = mnew;
                #pragma unroll
                for (int nt = 0; nt < 8; nt++) {
                    oacc[mt][nt][2*hp]   *= corr;
                    oacc[mt][nt][2*hp+1] *= corr;
                }
            }
        }

        // ---- pack P (fp16 A-fragments) and O += P @ V^T ----
        unsigned pa[2][4][4];
        #pragma unroll
        for (int mt = 0; mt < 2; mt++)
            #pragma unroll
            for (int kk = 0; kk < 4; kk++) {
                __half2 h0 = __floats2half2_rn(sacc[mt][2*kk][0],   sacc[mt][2*kk][1]);
                __half2 h1 = __floats2half2_rn(sacc[mt][2*kk][2],   sacc[mt][2*kk][3]);
                __half2 h2 = __floats2half2_rn(sacc[mt][2*kk+1][0], sacc[mt][2*kk+1][1]);
                __half2 h3 = __floats2half2_rn(sacc[mt][2*kk+1][2], sacc[mt][2*kk+1][3]);
                pa[mt][kk][0] = *(unsigned*)&h0; pa[mt][kk][1] = *(unsigned*)&h1;
                pa[mt][kk][2] = *(unsigned*)&h2; pa[mt][kk][3] = *(unsigned*)&h3;
            }
        #pragma unroll
        for (int kk = 0; kk < 4; kk++) {
            unsigned bf[8][2];
            #pragma unroll
            for (int p = 0; p < 4; p++) {
                unsigned r0, r1, r2, r3;
                asm volatile("ldmatrix.sync.aligned.m8n8.x4.shared.b16 {%0,%1,%2,%3}, [%4];"
                             : "=r"(r0), "=r"(r1), "=r"(r2), "=r"(r3)
                             : "r"(vb + boffB[p] + (unsigned)(kk * 32)));
                bf[2*p][0] = r0;   bf[2*p][1] = r2;
                bf[2*p+1][0] = r1; bf[2*p+1][1] = r3;
            }
            #pragma unroll
            for (int mt = 0; mt < 2; mt++)
                #pragma unroll
                for (int nt = 0; nt < 8; nt++)
                    asm volatile(
                        "mma.sync.aligned.m16n8k16.row.col.f32.f16.f16.f32 "
                        "{%0,%1,%2,%3}, {%4,%5,%6,%7}, {%8,%9}, {%0,%1,%2,%3};\n"
                        : "+f"(oacc[mt][nt][0]), "+f"(oacc[mt][nt][1]),
                          "+f"(oacc[mt][nt][2]), "+f"(oacc[mt][nt][3])
                        : "r"(pa[mt][kk][0]), "r"(pa[mt][kk][1]),
                          "r"(pa[mt][kk][2]), "r"(pa[mt][kk][3]),
                          "r"(bf[nt][0]), "r"(bf[nt][1]));
        }
        __syncthreads();
        if (s + 2 < St) issueKV((s + 2) * 64, s & 1);
    }

    // ---- normalize and store y ----
    #pragma unroll
    for (int mt = 0; mt < 2; mt++) {
        float inv0 = 1.f / l_s[mt][0], inv1 = 1.f / l_s[mt][1];
        #pragma unroll
        for (int nt = 0; nt < 8; nt++) {
            #pragma unroll
            for (int c = 0; c < 4; c++) {
                int r = q0 + warp * 32 + mt * 16 + g + ((c >> 1) << 3);
                int d = nt * 8 + 2 * tg + (c & 1);
                float v = oacc[mt][nt][c] * ((c >> 1) ? inv1 : inv0);
                g_y[(long long)(b * TDIM + r) * EDIM + h * HD + d] = __float2half_rn(v);
            }
        }
    }
}
#define SMEM_FA ((128 + 4*64) * FLDH * 2)   // 55296

// ======================= fp16 mma.sync GEMM (unchanged from R7) =======================
#define LDH 40

template<int NT16, int EP, int OT>
__global__ void __launch_bounds__(128, NT16 == 4 ? 2 : 3)
gemm_fp16(const __half* __restrict__ A, long long sAb, long long sAh,
          const __half* __restrict__ Bm, long long sBb, long long sBh,
          void* __restrict__ Cv, long long sCb, long long sCh,
          const float* __restrict__ bias,
          const float* __restrict__ res,
          int M, int N, int K, int lda, int ldb, int ldc,
          float alpha, int zdiv, int causal)
{
    extern __shared__ char smc[];
    const int BROWS = 32 * NT16;
    const int ASTG = 128 * LDH;
    const int BSTG = BROWS * LDH;
    __half* base = (__half*)smc;
    __half* AsB[2] = { base, base + ASTG };
    __half* BsB[2] = { base + 2 * ASTG, base + 2 * ASTG + BSTG };

    const int m0 = blockIdx.x * 128;
    const int n0 = blockIdx.y * BROWS;
    if (causal && n0 >= m0 + 128) return;

    int z = blockIdx.z;
    int zb = z / zdiv, zh = z % zdiv;
    A  += zb * sAb + zh * sAh;
    Bm += zb * sBb + zh * sBh;
    float* Cf = (float*)Cv + zb * sCb + zh * sCh;
    __half* Ch = (__half*)Cv + zb * sCb + zh * sCh;
    if (EP == 2) res += zb * sCb + zh * sCh;

    const int tid = threadIdx.x;
    const int warp = tid >> 5, lane = tid & 31;
    const int g = lane >> 2, tg = lane & 3;
    const int wm = warp >> 1, wn = warp & 1;
    const int quad = lane >> 3, rsel = lane & 7;

    float acc[4][2 * NT16][4];
    #pragma unroll
    for (int mt = 0; mt < 4; mt++)
        #pragma unroll
        for (int nt = 0; nt < 2 * NT16; nt++)
            #pragma unroll
            for (int c = 0; c < 4; c++) acc[mt][nt][c] = 0.f;

    unsigned aoff[4], boff[NT16];
    #pragma unroll
    for (int mt = 0; mt < 4; mt++)
        aoff[mt] = (unsigned)(((wm * 64 + mt * 16 + (quad & 1) * 8 + rsel) * LDH
                               + (quad >> 1) * 8) * 2);
    #pragma unroll
    for (int p = 0; p < NT16; p++)
        boff[p] = (unsigned)(((wn * 16 * NT16 + p * 16 + (quad & 1) * 8 + rsel) * LDH
                              + (quad >> 1) * 8) * 2);

    unsigned sA[2] = { (unsigned)__cvta_generic_to_shared(AsB[0]),
                       (unsigned)__cvta_generic_to_shared(AsB[1]) };
    unsigned sB[2] = { (unsigned)__cvta_generic_to_shared(BsB[0]),
                       (unsigned)__cvta_generic_to_shared(BsB[1]) };

    auto issue = [&](int k0, int buf) {
        unsigned ab = sA[buf], bb = sB[buf];
        #pragma unroll
        for (int it = 0; it < 4; it++) {
            int idx = tid + it * 128;
            int row = idx >> 2, seg = idx & 3;
            const __half* src = &A[(long long)(m0 + row) * lda + k0 + seg * 8];
            unsigned dst = ab + (unsigned)(row * LDH + seg * 8) * 2u;
            asm volatile("cp.async.cg.shared.global [%0], [%1], 16;\n"
                         :: "r"(dst), "l"(src));
        }
        #pragma unroll
        for (int it = 0; it < NT16; it++) {
            int idx = tid + it * 128;
            int nn = idx >> 2, seg = idx & 3;
            int gn = n0 + nn;
            const __half* src = &Bm[(long long)gn * ldb + k0 + seg * 8];
            int sz = (gn < N) ? 16 : 0;
            if (!sz) src = Bm;
            unsigned dst = bb + (unsigned)(nn * LDH + seg * 8) * 2u;
            asm volatile("cp.async.cg.shared.global [%0], [%1], 16, %2;\n"
                         :: "r"(dst), "l"(src), "r"(sz));
        }
        asm volatile("cp.async.commit_group;\n" ::: "memory");
    };

    const int S = K >> 5;
    issue(0, 0);
    if (S > 1) issue(32, 1);

    for (int s = 0; s < S; s++) {
        if (s + 1 < S) asm volatile("cp.async.wait_group 1;\n" ::: "memory");
        else           asm volatile("cp.async.wait_group 0;\n" ::: "memory");
        __syncthreads();
        unsigned abase = sA[s & 1], bbase = sB[s & 1];
        #pragma unroll
        for (int kk = 0; kk < 2; kk++) {
            unsigned af[4][4];
            #pragma unroll
            for (int mt = 0; mt < 4; mt++) {
                asm volatile("ldmatrix.sync.aligned.m8n8.x4.shared.b16 {%0,%1,%2,%3}, [%4];"
                             : "=r"(af[mt][0]), "=r"(af[mt][1]), "=r"(af[mt][2]), "=r"(af[mt][3])
                             : "r"(abase + aoff[mt] + (unsigned)(kk * 32)));
            }
            unsigned bf[2 * NT16][2];
            #pragma unroll
            for (int p = 0; p < NT16; p++) {
                unsigned r0, r1, r2, r3;
                asm volatile("ldmatrix.sync.aligned.m8n8.x4.shared.b16 {%0,%1,%2,%3}, [%4];"
                             : "=r"(r0), "=r"(r1), "=r"(r2), "=r"(r3)
                             : "r"(bbase + boff[p] + (unsigned)(kk * 32)));
                bf[2 * p][0] = r0;     bf[2 * p][1] = r2;
                bf[2 * p + 1][0] = r1; bf[2 * p + 1][1] = r3;
            }
            #pragma unroll
            for (int mt = 0; mt < 4; mt++)
                #pragma unroll
                for (int nt = 0; nt < 2 * NT16; nt++) {
                    asm volatile(
                        "mma.sync.aligned.m16n8k16.row.col.f32.f16.f16.f32 "
                        "{%0,%1,%2,%3}, {%4,%5,%6,%7}, {%8,%9}, {%0,%1,%2,%3};\n"
                        : "+f"(acc[mt][nt][0]), "+f"(acc[mt][nt][1]),
                          "+f"(acc[mt][nt][2]), "+f"(acc[mt][nt][3])
                        : "r"(af[mt][0]), "r"(af[mt][1]), "r"(af[mt][2]), "r"(af[mt][3]),
                          "r"(bf[nt][0]), "r"(bf[nt][1]));
                }
        }
        __syncthreads();
        if (s + 2 < S) issue((s + 2) << 5, s & 1);
    }

    #pragma unroll
    for (int mt = 0; mt < 4; mt++) {
        #pragma unroll
        for (int nt = 0; nt < 2 * NT16; nt++) {
            int col0 = n0 + wn * 16 * NT16 + nt * 8 + 2 * tg;
            int r0 = m0 + wm * 64 + mt * 16 + g;
            #pragma unroll
            for (int ci = 0; ci < 4; ci++) {
                int r = r0 + (ci >> 1) * 8;
                int c = col0 + (ci & 1);
                if (c >= N) continue;
                float v = alpha * acc[mt][nt][ci];
                if (bias) v += bias[c];
                if (EP == 1) {
                    float u = v;
                    v = 0.5f * u * (1.f + tanhf(0.7978845608028654f * (u + 0.044715f * u * u * u)));
                }
                if (EP == 2) v += res[(long long)r * ldc + c];
                if (OT == 0) Cf[(long long)r * ldc + c] = v;
                else         Ch[(long long)r * ldc + c] = __float2half_rn(v);
            }
        }
    }
}

#define SMEM_H4 (2 * (128*LDH + 128*LDH) * 2)   // 40960
#define SMEM_H2 (2 * (128*LDH + 64*LDH) * 2)    // 30720

extern "C" void kernel_launch(void* const* d_in, const int* in_sizes, int n_in,
                              void* d_out, int out_size) {
    const int*   idx    = (const int*)  d_in[0];
    const float* wte    = (const float*)d_in[1];
    const float* wpe    = (const float*)d_in[2];
    const float* ln1_w  = (const float*)d_in[3];
    const float* ln1_b  = (const float*)d_in[4];
    const float* attn_w = (const float*)d_in[5];
    const float* attn_b = (const float*)d_in[6];
    const float* atp_w  = (const float*)d_in[7];
    const float* atp_b  = (const float*)d_in[8];
    const float* ln2_w  = (const float*)d_in[9];
    const float* ln2_b  = (const float*)d_in[10];
    const float* fc_w   = (const float*)d_in[11];
    const float* fc_b   = (const float*)d_in[12];
    const float* pr_w   = (const float*)d_in[13];
    const float* pr_b   = (const float*)d_in[14];
    const float* lnf_w  = (const float*)d_in[15];
    const float* lnf_b  = (const float*)d_in[16];
    float* out = (float*)d_out;

    float *gx; __half *gh, *gqkv, *gy, *gm;
    __half *cw_attn, *cw_atp, *cw_fc, *cw_pr, *cw_wte;
    cudaGetSymbolAddress((void**)&gx,    g_x);
    cudaGetSymbolAddress((void**)&gh,    g_h);
    cudaGetSymbolAddress((void**)&gqkv,  g_qkv);
    cudaGetSymbolAddress((void**)&gy,    g_y);
    cudaGetSymbolAddress((void**)&gm,    g_m);
    cudaGetSymbolAddress((void**)&cw_attn, c_attn_w);
    cudaGetSymbolAddress((void**)&cw_atp,  c_atp_w);
    cudaGetSymbolAddress((void**)&cw_fc,   c_fc_w);
    cudaGetSymbolAddress((void**)&cw_pr,   c_pr_w);
    cudaGetSymbolAddress((void**)&cw_wte,  c_wte);

    cudaFuncSetAttribute(gemm_fp16<4,0,0>, cudaFuncAttributeMaxDynamicSharedMemorySize, SMEM_H4);
    cudaFuncSetAttribute(gemm_fp16<4,0,1>, cudaFuncAttributeMaxDynamicSharedMemorySize, SMEM_H4);
    cudaFuncSetAttribute(gemm_fp16<4,1,1>, cudaFuncAttributeMaxDynamicSharedMemorySize, SMEM_H4);
    cudaFuncSetAttribute(gemm_fp16<2,2,0>, cudaFuncAttributeMaxDynamicSharedMemorySize, SMEM_H2);
    cudaFuncSetAttribute(flash_attn, cudaFuncAttributeMaxDynamicSharedMemorySize, SMEM_FA);

    const float scale = 0.03608439182435161f;  // 1/sqrt(E)

    // ---- weight prepass ----
    {
        dim3 b(32, 8);
        transpose_half<<<dim3(3*EDIM/32, EDIM/32, NL), b>>>(attn_w, cw_attn, EDIM, 3*EDIM);
        transpose_half<<<dim3(EDIM/32,   EDIM/32, NL), b>>>(atp_w,  cw_atp,  EDIM, EDIM);
        transpose_half<<<dim3(4*EDIM/32, EDIM/32, NL), b>>>(fc_w,   cw_fc,   EDIM, 4*EDIM);
        transpose_half<<<dim3(EDIM/32, 4*EDIM/32, NL), b>>>(pr_w,   cw_pr,   4*EDIM, EDIM);
        half_convert4<<<8192, 256>>>((const float4*)wte, (__half2*)cw_wte,
                                     (int)((long long)VDIM*EDIM/4));
    }

    embed_kernel<<<BT, 256>>>(idx, wte, wpe);

    for (int l = 0; l < NL; l++) {
        layernorm_kernel<<<BT, 256>>>(gx, gh, ln1_w + l * EDIM, ln1_b + l * EDIM);

        // qkv = h @ attn_w + attn_b  -> half
        {
            dim3 g(BT / 128, 3 * EDIM / 128, 1);
            gemm_fp16<4, 0, 1><<<g, 128, SMEM_H4>>>(gh, 0, 0,
                                      cw_attn + (long long)l * EDIM * 3 * EDIM, 0, 0,
                                      gqkv, 0, 0,
                                      attn_b + l * 3 * EDIM, nullptr,
                                      BT, 3 * EDIM, EDIM, EDIM, EDIM, 3 * EDIM,
                                      1.f, 1, 0);
        }
        // V transpose, then fused attention -> g_y (half)
        v_transpose<<<dim3(TDIM / 32, HD / 32, BDIM * NH), dim3(32, 8)>>>();
        flash_attn<<<dim3(TDIM / 128, BDIM * NH), 128, SMEM_FA>>>(scale);

        // x = x + y @ atp_w + atp_b  -> float
        {
            dim3 g(BT / 128, EDIM / 64, 1);
            gemm_fp16<2, 2, 0><<<g, 128, SMEM_H2>>>(gy, 0, 0,
                                      cw_atp + (long long)l * EDIM * EDIM, 0, 0,
                                      gx, 0, 0,
                                      atp_b + l * EDIM, gx,
                                      BT, EDIM, EDIM, EDIM, EDIM, EDIM,
                                      1.f, 1, 0);
        }
        layernorm_kernel<<<BT, 256>>>(gx, gh, ln2_w + l * EDIM, ln2_b + l * EDIM);

        // m = gelu(h @ fc_w + fc_b) -> half
        {
            dim3 g(BT / 128, 4 * EDIM / 128, 1);
            gemm_fp16<4, 1, 1><<<g, 128, SMEM_H4>>>(gh, 0, 0,
                                      cw_fc + (long long)l * EDIM * 4 * EDIM, 0, 0,
                                      gm, 0, 0,
                                      fc_b + l * 4 * EDIM, nullptr,
                                      BT, 4 * EDIM, EDIM, EDIM, EDIM, 4 * EDIM,
                                      1.f, 1, 0);
        }
        // x = x + m @ pr_w + pr_b  -> float
        {
            dim3 g(BT / 128, EDIM / 64, 1);
            gemm_fp16<2, 2, 0><<<g, 128, SMEM_H2>>>(gm, 0, 0,
                                      cw_pr + (long long)l * 4 * EDIM * EDIM, 0, 0,
                                      gx, 0, 0,
                                      pr_b + l * EDIM, gx,
                                      BT, EDIM, 4 * EDIM, 4 * EDIM, 4 * EDIM, EDIM,
                                      1.f, 1, 0);
        }
    }

    layernorm_kernel<<<BT, 256>>>(gx, gh, lnf_w, lnf_b);

    // logits = h @ wte^T -> float
    {
        dim3 g(BT / 128, (VDIM + 127) / 128, 1);
        gemm_fp16<4, 0, 0><<<g, 128, SMEM_H4>>>(gh, 0, 0,
                                  cw_wte, 0, 0,
                                  out, 0, 0,
                                  nullptr, nullptr,
                                  BT, VDIM, EDIM, EDIM, EDIM, VDIM,
                                  1.f, 1, 0);
    }
}